// round 7
// baseline (speedup 1.0000x reference)
#include <cuda_runtime.h>
#include <math.h>

#define B 32
#define L 256
#define EXT 64
#define H 256
#define M 64
#define NMEM 4096
#define NST 32
#define OUT 64

typedef unsigned long long ull;

// ---------------- scratch (device globals; no allocation) ----------------
__device__ float g_xm[B * H];
__device__ float g_kw[B * M], g_e[B * M], g_a[B * M], g_kr[B * M];
__device__ float g_pw[B * 8], g_pr[B * 8];
__device__ __align__(16) float g_score[B * NMEM];
__device__ __align__(16) float g_st2[(size_t)B * NMEM * 8];  // d1,d2,ss,s2 | s3,s4,s5,_
__device__ __align__(16) float g_ww[B * NMEM];
__device__ __align__(16) float g_wr[B * NMEM];
__device__ float g_rpart[B * 32 * M];
__device__ int g_cntE[B], g_cntP[B], g_cntR[B];

// ---------------- helpers ----------------
__device__ __forceinline__ float wredsum(float v) {
    #pragma unroll
    for (int o = 16; o > 0; o >>= 1) v += __shfl_xor_sync(0xffffffffu, v, o);
    return v;
}
__device__ __forceinline__ float gredsum16(float v) {
    #pragma unroll
    for (int o = 8; o > 0; o >>= 1) v += __shfl_xor_sync(0xffffffffu, v, o);
    return v;
}
__device__ __forceinline__ float wredmax(float v) {
    #pragma unroll
    for (int o = 16; o > 0; o >>= 1) v = fmaxf(v, __shfl_xor_sync(0xffffffffu, v, o));
    return v;
}
// 256-thread (8-warp) block reductions
__device__ __forceinline__ float blk256_sum(float v, float* red, float* bc, int lane, int w) {
    v = wredsum(v);
    if (lane == 0) red[w] = v;
    __syncthreads();
    if (w == 0) {
        float x = (lane < 8) ? red[lane] : 0.f;
        #pragma unroll
        for (int o = 4; o > 0; o >>= 1) x += __shfl_xor_sync(0xffffffffu, x, o);
        if (lane == 0) *bc = x;
    }
    __syncthreads();
    return *bc;
}
__device__ __forceinline__ float blk256_max(float v, float* red, float* bc, int lane, int w) {
    v = wredmax(v);
    if (lane == 0) red[w] = v;
    __syncthreads();
    if (w == 0) {
        float x = (lane < 8) ? red[lane] : __int_as_float(0xff800000);
        #pragma unroll
        for (int o = 4; o > 0; o >>= 1) x = fmaxf(x, __shfl_xor_sync(0xffffffffu, x, o));
        if (lane == 0) *bc = x;
    }
    __syncthreads();
    return *bc;
}
__device__ __forceinline__ float softplus_f(float x) {
    return (x > 20.f) ? x : log1pf(expf(x));
}
__device__ __forceinline__ float sigmoid_f(float x) {
    return 1.f / (1.f + expf(-x));
}
__device__ __forceinline__ ull pack2(float lo, float hi) {
    ull r; asm("mov.b64 %0,{%1,%2};" : "=l"(r) : "f"(lo), "f"(hi)); return r;
}
__device__ __forceinline__ void unpack2(ull v, float& lo, float& hi) {
    asm("mov.b64 {%0,%1},%2;" : "=f"(lo), "=f"(hi) : "l"(v));
}
__device__ __forceinline__ ull f2fma(ull a, ull b, ull c) {
    ull d; asm("fma.rn.f32x2 %0,%1,%2,%3;" : "=l"(d) : "l"(a), "l"(b), "l"(c)); return d;
}
__device__ __forceinline__ ull f2mul(ull a, ull b) {
    ull d; asm("mul.rn.f32x2 %0,%1,%2;" : "=l"(d) : "l"(a), "l"(b)); return d;
}

// ============ Kernel 1: encoder GEMM + S4D closed-form + heads tail ============
// grid (B, H/16), block 256
__global__ void __launch_bounds__(256) k_encode_scan(
    const float* __restrict__ x, const float* __restrict__ r0,
    const float* __restrict__ sr0, const float* __restrict__ si0,
    const float* __restrict__ encW, const float* __restrict__ encb,
    const float* __restrict__ log_dt, const float* __restrict__ logAr,
    const float* __restrict__ Aim, const float* __restrict__ Cre,
    const float* __restrict__ Cim, const float* __restrict__ Dv,
    const float* __restrict__ writeW, const float* __restrict__ writeb,
    const float* __restrict__ readW,  const float* __restrict__ readb)
{
    __shared__ float xsT[64 * 66];
    __shared__ ull   Wd[128 * 16];
    __shared__ ull   us2[16 * 64];
    __shared__ float xsh[H];
    __shared__ float sow[3 * M + 6];
    __shared__ float sorh[M + 6];
    __shared__ int   isLast;

    int b = blockIdx.x, hg = blockIdx.y;
    int t = threadIdx.x, w = t >> 5, lane = t & 31;
    int sel = lane >> 4, p = lane & 15;
    int slot = w * 2 + sel;
    int h = hg * 16 + slot;

    for (int i = t; i < 128 * 16; i += 256) {
        int e = i >> 4, sl = i & 15;
        float wv = encW[e * H + hg * 16 + sl];
        Wd[i] = pack2(wv, wv);
    }
    __syncthreads();

    float c = 0.f;
    #pragma unroll
    for (int m = p; m < M; m += 16) {
        float lo, hi; unpack2(Wd[(EXT + m) * 16 + slot], lo, hi);
        c += r0[b * M + m] * lo;
    }
    c = gredsum16(c) + encb[h];
    ull cdup = pack2(c, c);

    int n0 = 2 * p;
    float dt = expf(log_dt[h]);
    float dAr_s[2], dAi_s[2];
    #pragma unroll
    for (int s = 0; s < 2; s++) {
        int idx = h * NST + n0 + s;
        float ar = -expf(logAr[idx]);
        float ai = Aim[idx];
        float er = expf(dt * ar);
        dAr_s[s] = er * cosf(dt * ai);
        dAi_s[s] = er * sinf(dt * ai);
    }
    ull dAr2  = pack2(dAr_s[0], dAr_s[1]);
    ull dAi2  = pack2(dAi_s[0], dAi_s[1]);
    ull ndAi2 = pack2(-dAi_s[0], -dAi_s[1]);

    ull tr2 = 0, ti2 = 0;
    float usum = 0.f;
    int base = slot * 64;

    for (int ch = 0; ch < 4; ch++) {
        __syncthreads();
        int l0 = ch * 64;
        for (int i = t; i < 64 * 64; i += 256) {
            int rr = i >> 6, cc = i & 63;
            xsT[cc * 66 + rr] = x[((b * L) + (l0 + rr)) * EXT + cc];
        }
        __syncthreads();

        {
            ull acc0 = cdup, acc1 = cdup;
            #pragma unroll
            for (int e = 0; e < EXT; e++) {
                ull wv = Wd[e * 16 + slot];
                acc0 = f2fma(wv, *(const ull*)&xsT[e * 66 + 2 * p], acc0);
                acc1 = f2fma(wv, *(const ull*)&xsT[e * 66 + 2 * (p + 16)], acc1);
            }
            float u0, u1; unpack2(acc0, u0, u1);
            us2[base + 2 * p]     = pack2(u0, u0);
            us2[base + 2 * p + 1] = pack2(u1, u1);
            usum += u0 + u1;
            unpack2(acc1, u0, u1);
            us2[base + 2 * (p + 16)]     = pack2(u0, u0);
            us2[base + 2 * (p + 16) + 1] = pack2(u1, u1);
            usum += u0 + u1;
        }
        __syncwarp();

        #pragma unroll 8
        for (int j = 0; j < 64; j++) {
            ull u2 = us2[base + j];
            ull tA = f2fma(ndAi2, ti2, u2);
            ull trn = f2fma(dAr2, tr2, tA);
            ull tB = f2mul(dAr2, ti2);
            ti2 = f2fma(dAi2, tr2, tB);
            tr2 = trn;
        }
        __syncwarp();
    }

    usum = gredsum16(usum);

    float Trp[2], Tip[2];
    unpack2(tr2, Trp[0], Trp[1]);
    unpack2(ti2, Tip[0], Tip[1]);
    float val = 0.f;
    #pragma unroll
    for (int s = 0; s < 2; s++) {
        int idx = h * NST + n0 + s;
        float ar = -expf(logAr[idx]);
        float ai = Aim[idx];
        float dar = dAr_s[s], dai = dAi_s[s];
        float xr = dar * Trp[s] - dai * Tip[s];
        float xi = dai * Trp[s] + dar * Tip[s];
        float wr = usum - xr, wi = -xi;
        float den = ar * ar + ai * ai;
        float invr = -ar / den, invi = ai / den;
        float Sr = invr * wr - invi * wi;
        float Si = invr * wi + invi * wr;
        float s0r = sr0[b * H * NST + idx], s0i = si0[b * H * NST + idx];
        if (s0r != 0.f || s0i != 0.f) {
            float eL = expf((float)L * dt * ar);
            float phi = (float)L * dt * ai;
            float dALr = eL * cosf(phi), dALi = eL * sinf(phi);
            float numr = 1.f - dALr, numi = -dALi;
            float omr = 1.f - dar, omi = -dai;
            float r2 = omr * omr + omi * omi;
            float qr = (numr * omr + numi * omi) / r2;
            float qi = (numi * omr - numr * omi) / r2;
            float gr = dar * qr - dai * qi;
            float gi = dai * qr + dar * qi;
            Sr += gr * s0r - gi * s0i;
            Si += gr * s0i + gi * s0r;
        }
        val += Cre[idx] * Sr - Cim[idx] * Si;
    }
    val = gredsum16(val);
    if (p == 0)
        g_xm[b * H + h] = (2.f * val + (Dv[h] + 1.f) * usum) * (1.f / (float)L);

    // ---- heads tail: last block of this batch ----
    __threadfence();
    __syncthreads();
    if (t == 0) {
        int cpl = atomicAdd(&g_cntE[b], 1);
        isLast = (cpl == 15);
        if (cpl == 15) g_cntE[b] = 0;
    }
    __syncthreads();
    if (!isLast) return;
    __threadfence();

    xsh[t] = g_xm[b * H + t];
    __syncthreads();

    for (int jj = t; jj < 268; jj += 256) {
        if (jj < 198) {
            float acc = writeb[jj];
            for (int hh = 0; hh < H; hh++) acc = fmaf(xsh[hh], writeW[hh * 198 + jj], acc);
            sow[jj] = acc;
        } else {
            int j = jj - 198;
            float acc = readb[j];
            for (int hh = 0; hh < H; hh++) acc = fmaf(xsh[hh], readW[hh * 70 + j], acc);
            sorh[j] = acc;
        }
    }
    __syncthreads();

    if (t < M) {
        g_kw[b * M + t] = sow[t];
        g_e[b * M + t]  = sigmoid_f(sow[M + 6 + t]);
        g_a[b * M + t]  = sow[2 * M + 6 + t];
        g_kr[b * M + t] = sorh[t];
    } else if (t == M) {
        float beta = softplus_f(sow[M]);
        float g    = sigmoid_f(sow[M + 1]);
        float m3 = fmaxf(sow[M + 2], fmaxf(sow[M + 3], sow[M + 4]));
        float e0 = expf(sow[M + 2] - m3), e1 = expf(sow[M + 3] - m3), e2 = expf(sow[M + 4] - m3);
        float Z = e0 + e1 + e2;
        float gamma = 1.f + softplus_f(sow[M + 5]);
        float nk = 0.f;
        for (int m = 0; m < M; m++) { float v = sow[m]; nk += v * v; }
        g_pw[b * 8 + 0] = beta; g_pw[b * 8 + 1] = g;
        g_pw[b * 8 + 2] = e0 / Z; g_pw[b * 8 + 3] = e1 / Z; g_pw[b * 8 + 4] = e2 / Z;
        g_pw[b * 8 + 5] = gamma; g_pw[b * 8 + 6] = sqrtf(nk);
    } else if (t == M + 1) {
        float beta = softplus_f(sorh[M]);
        float g    = sigmoid_f(sorh[M + 1]);
        float m3 = fmaxf(sorh[M + 2], fmaxf(sorh[M + 3], sorh[M + 4]));
        float e0 = expf(sorh[M + 2] - m3), e1 = expf(sorh[M + 3] - m3), e2 = expf(sorh[M + 4] - m3);
        float Z = e0 + e1 + e2;
        float gamma = 1.f + softplus_f(sorh[M + 5]);
        float nk = 0.f;
        for (int m = 0; m < M; m++) { float v = sorh[m]; nk += v * v; }
        g_pr[b * 8 + 0] = beta; g_pr[b * 8 + 1] = g;
        g_pr[b * 8 + 2] = e0 / Z; g_pr[b * 8 + 3] = e1 / Z; g_pr[b * 8 + 4] = e2 / Z;
        g_pr[b * 8 + 5] = gamma; g_pr[b * 8 + 6] = sqrtf(nk);
    } else if (t == M + 2) {
        float akr = 0.f, aa = 0.f;
        for (int m = 0; m < M; m++) {
            float av = sow[2 * M + 6 + m];
            akr = fmaf(av, sorh[m], akr);
            aa  = fmaf(av, av, aa);
        }
        g_pr[b * 8 + 7] = akr;
        g_pw[b * 8 + 7] = aa;
    }
}

// ============ Kernel 2: mem pass (score + stats) + full addressing tail ============
// grid 512 (16 blocks/batch), block 256
__global__ void __launch_bounds__(256) k_pass1_addr(
    const float* __restrict__ mem,
    const float* __restrict__ ww0, const float* __restrict__ wr0)
{
    __shared__ float kw[M], kr_[M], ekr[M], ev[M], e2v[M], av[M], eav[M];
    __shared__ __align__(16) float sc[NMEM];
    __shared__ __align__(16) float wg[NMEM];
    __shared__ float red[8];
    __shared__ float bcast;
    __shared__ int   isLast;

    int t = threadIdx.x;
    int lane = t & 31, w = t >> 5;
    int b = blockIdx.x >> 4;
    int row = blockIdx.x * 256 + t;

    if (t < M) {
        float kwv = g_kw[b * M + t];
        float krv = g_kr[b * M + t];
        float e_  = g_e[b * M + t];
        float a_  = g_a[b * M + t];
        kw[t] = kwv; kr_[t] = krv; ekr[t] = e_ * krv;
        ev[t] = e_; e2v[t] = e_ * e_; av[t] = a_; eav[t] = e_ * a_;
    }
    __syncthreads();

    {
        const float4* mp = (const float4*)(mem + (size_t)row * M);
        float dw = 0.f, ss = 0.f, d1 = 0.f, d2 = 0.f, s2 = 0.f, s3 = 0.f, s4 = 0.f, s5 = 0.f;
        #pragma unroll
        for (int i = 0; i < 16; i++) {
            float4 v = mp[i];
            int m = i * 4;
            #pragma unroll
            for (int j = 0; j < 4; j++) {
                float vv = (&v.x)[j];
                int mm = m + j;
                float v2 = vv * vv;
                dw = fmaf(vv, kw[mm],  dw);
                ss += v2;
                d1 = fmaf(vv, kr_[mm], d1);
                d2 = fmaf(vv, ekr[mm], d2);
                s2 = fmaf(v2, ev[mm],  s2);
                s3 = fmaf(v2, e2v[mm], s3);
                s4 = fmaf(vv, av[mm],  s4);
                s5 = fmaf(vv, eav[mm], s5);
            }
        }
        float beta = g_pw[b * 8 + 0], knw = g_pw[b * 8 + 6];
        g_score[row] = beta * dw / (sqrtf(ss) * knw + 1e-16f);
        float4 st0 = make_float4(d1, d2, ss, s2);
        float4 st1 = make_float4(s3, s4, s5, 0.f);
        *(float4*)&g_st2[(size_t)row * 8]     = st0;
        *(float4*)&g_st2[(size_t)row * 8 + 4] = st1;
    }

    // ---- addressing tail: last block of this batch ----
    __threadfence();
    __syncthreads();
    if (t == 0) {
        int cpl = atomicAdd(&g_cntP[b], 1);
        isLast = (cpl == 15);
        if (cpl == 15) g_cntP[b] = 0;
    }
    __syncthreads();
    if (!isLast) return;
    __threadfence();

    // ======== phase A: write addressing ========
    {
        float g = g_pw[b * 8 + 1], q0 = g_pw[b * 8 + 2], q1 = g_pw[b * 8 + 3];
        float q2 = g_pw[b * 8 + 4], gamma = g_pw[b * 8 + 5];

        float lm = __int_as_float(0xff800000);
        #pragma unroll
        for (int i = 0; i < 4; i++) {
            int f = t + 256 * i;
            float4 v = *(const float4*)&g_score[b * NMEM + 4 * f];
            *(float4*)&sc[4 * f] = v;
            lm = fmaxf(lm, fmaxf(fmaxf(v.x, v.y), fmaxf(v.z, v.w)));
        }
        float bm = blk256_max(lm, red, &bcast, lane, w);

        float ls = 0.f;
        #pragma unroll
        for (int i = 0; i < 4; i++) {
            int f = t + 256 * i;
            float4 v = *(float4*)&sc[4 * f];
            v.x = __expf(v.x - bm); v.y = __expf(v.y - bm);
            v.z = __expf(v.z - bm); v.w = __expf(v.w - bm);
            *(float4*)&sc[4 * f] = v;
            ls += v.x + v.y + v.z + v.w;
        }
        float Z = blk256_sum(ls, red, &bcast, lane, w);
        float gZ = g / Z, og = 1.f - g;

        #pragma unroll
        for (int i = 0; i < 4; i++) {
            int f = t + 256 * i;
            float4 pv = *(float4*)&sc[4 * f];
            float4 w0 = *(const float4*)&ww0[b * NMEM + 4 * f];
            float4 r;
            r.x = fmaf(gZ, pv.x, og * w0.x);
            r.y = fmaf(gZ, pv.y, og * w0.y);
            r.z = fmaf(gZ, pv.z, og * w0.z);
            r.w = fmaf(gZ, pv.w, og * w0.w);
            *(float4*)&wg[4 * f] = r;
        }
        __syncthreads();

        float lp = 0.f;
        #pragma unroll
        for (int i = 0; i < 4; i++) {
            int f = t + 256 * i;
            #pragma unroll
            for (int j = 0; j < 4; j++) {
                int n = 4 * f + j;
                float wt = q0 * wg[(n - 1) & (NMEM - 1)] + q1 * wg[n] + q2 * wg[(n + 1) & (NMEM - 1)];
                float wp = (wt > 0.f) ? __powf(wt, gamma) : 0.f;
                sc[n] = wp; lp += wp;
            }
        }
        float Zp = blk256_sum(lp, red, &bcast, lane, w) + 1e-16f;
        float iZp = 1.f / Zp;

        #pragma unroll
        for (int i = 0; i < 4; i++) {
            int f = t + 256 * i;
            float4 v = *(float4*)&sc[4 * f];
            v.x *= iZp; v.y *= iZp; v.z *= iZp; v.w *= iZp;
            *(float4*)&sc[4 * f] = v;                       // keep w_w in smem
            *(float4*)&g_ww[b * NMEM + 4 * f] = v;          // store for readvec
        }
        __syncthreads();
    }

    // ======== phase B: read score from stats + read addressing ========
    {
        float beta = g_pr[b * 8 + 0], knr = g_pr[b * 8 + 6];
        float akr  = g_pr[b * 8 + 7], aa  = g_pw[b * 8 + 7];
        float g = g_pr[b * 8 + 1], q0 = g_pr[b * 8 + 2], q1 = g_pr[b * 8 + 3];
        float q2 = g_pr[b * 8 + 4], gamma = g_pr[b * 8 + 5];

        float lm = __int_as_float(0xff800000);
        #pragma unroll
        for (int i = 0; i < 4; i++) {
            int f = t + 256 * i;
            #pragma unroll
            for (int j = 0; j < 4; j++) {
                int n = 4 * f + j;
                size_t rw = (size_t)(b * NMEM + n) * 8;
                float4 st0 = *(const float4*)&g_st2[rw];
                float4 st1 = *(const float4*)&g_st2[rw + 4];
                float wwv = sc[n];
                float dot = st0.x - wwv * (st0.y - akr);
                float n2 = st0.z + wwv * (2.f * (st1.y - st0.w))
                         + wwv * wwv * (st1.x - 2.f * st1.z + aa);
                float v = beta * dot / (sqrtf(fmaxf(n2, 0.f)) * knr + 1e-16f);
                wg[n] = v; lm = fmaxf(lm, v);
            }
        }
        float bm = blk256_max(lm, red, &bcast, lane, w);

        float ls = 0.f;
        #pragma unroll
        for (int i = 0; i < 4; i++) {
            int f = t + 256 * i;
            float4 v = *(float4*)&wg[4 * f];
            v.x = __expf(v.x - bm); v.y = __expf(v.y - bm);
            v.z = __expf(v.z - bm); v.w = __expf(v.w - bm);
            *(float4*)&wg[4 * f] = v;
            ls += v.x + v.y + v.z + v.w;
        }
        float Z = blk256_sum(ls, red, &bcast, lane, w);
        float gZ = g / Z, og = 1.f - g;

        #pragma unroll
        for (int i = 0; i < 4; i++) {
            int f = t + 256 * i;
            float4 pv = *(float4*)&wg[4 * f];
            float4 w0 = *(const float4*)&wr0[b * NMEM + 4 * f];
            float4 r;
            r.x = fmaf(gZ, pv.x, og * w0.x);
            r.y = fmaf(gZ, pv.y, og * w0.y);
            r.z = fmaf(gZ, pv.z, og * w0.z);
            r.w = fmaf(gZ, pv.w, og * w0.w);
            *(float4*)&sc[4 * f] = r;
        }
        __syncthreads();

        float lp = 0.f;
        #pragma unroll
        for (int i = 0; i < 4; i++) {
            int f = t + 256 * i;
            #pragma unroll
            for (int j = 0; j < 4; j++) {
                int n = 4 * f + j;
                float wt = q0 * sc[(n - 1) & (NMEM - 1)] + q1 * sc[n] + q2 * sc[(n + 1) & (NMEM - 1)];
                float wp = (wt > 0.f) ? __powf(wt, gamma) : 0.f;
                wg[n] = wp; lp += wp;
            }
        }
        float Zp = blk256_sum(lp, red, &bcast, lane, w) + 1e-16f;
        float iZp = 1.f / Zp;

        #pragma unroll
        for (int i = 0; i < 4; i++) {
            int f = t + 256 * i;
            float4 v = *(float4*)&wg[4 * f];
            v.x *= iZp; v.y *= iZp; v.z *= iZp; v.w *= iZp;
            *(float4*)&g_wr[b * NMEM + 4 * f] = v;
        }
    }
}

// ============ Kernel 3: r = w_r . mem2 + decoder tail ============
// grid (B, 32), block 256
__global__ void __launch_bounds__(256) k_readvec_dec(
    const float* __restrict__ mem, const float* __restrict__ decW,
    const float* __restrict__ decb, float* __restrict__ out)
{
    __shared__ float es4[M], as4[M];
    __shared__ float part[16][M + 4];
    __shared__ float xsd[H];
    __shared__ float rs[M];
    __shared__ int   isLast;

    int b = blockIdx.x, chunk = blockIdx.y;
    int t = threadIdx.x;
    int m4 = t & 15;
    int rgrp = t >> 4;
    if (t < M) { es4[t] = g_e[b * M + t]; as4[t] = g_a[b * M + t]; }
    __syncthreads();

    int m = m4 * 4;
    float4 ev = make_float4(es4[m], es4[m + 1], es4[m + 2], es4[m + 3]);
    float4 av = make_float4(as4[m], as4[m + 1], as4[m + 2], as4[m + 3]);

    float4 acc = make_float4(0.f, 0.f, 0.f, 0.f);
    int n0 = chunk * 128;
    #pragma unroll
    for (int k = 0; k < 8; k++) {
        int n = n0 + rgrp + 16 * k;
        int row = b * NMEM + n;
        float wwv = g_ww[row], wrv = g_wr[row];
        float4 v = *(const float4*)(mem + (size_t)row * M + m);
        float4 v2;
        v2.x = fmaf(v.x, 1.f - wwv * ev.x, wwv * av.x);
        v2.y = fmaf(v.y, 1.f - wwv * ev.y, wwv * av.y);
        v2.z = fmaf(v.z, 1.f - wwv * ev.z, wwv * av.z);
        v2.w = fmaf(v.w, 1.f - wwv * ev.w, wwv * av.w);
        acc.x = fmaf(wrv, v2.x, acc.x);
        acc.y = fmaf(wrv, v2.y, acc.y);
        acc.z = fmaf(wrv, v2.z, acc.z);
        acc.w = fmaf(wrv, v2.w, acc.w);
    }
    *(float4*)&part[rgrp][m] = acc;
    __syncthreads();

    if (t < M) {
        float s = 0.f;
        #pragma unroll
        for (int r = 0; r < 16; r++) s += part[r][t];
        g_rpart[(b * 32 + chunk) * M + t] = s;
    }

    // ---- decoder tail: last chunk-block of this batch ----
    __threadfence();
    __syncthreads();
    if (t == 0) {
        int cpl = atomicAdd(&g_cntR[b], 1);
        isLast = (cpl == 31);
        if (cpl == 31) g_cntR[b] = 0;
    }
    __syncthreads();
    if (!isLast) return;
    __threadfence();

    xsd[t] = g_xm[b * H + t];
    if (t < M) {
        float s = 0.f;
        #pragma unroll
        for (int c = 0; c < 32; c++) s += g_rpart[(b * 32 + c) * M + t];
        rs[t] = s;
    }
    __syncthreads();
    if (t < OUT) {
        float acc2 = decb[t];
        for (int hh = 0; hh < H; hh++) acc2 = fmaf(xsd[hh], decW[hh * OUT + t], acc2);
        for (int mm = 0; mm < M; mm++) acc2 = fmaf(rs[mm], decW[(H + mm) * OUT + t], acc2);
        out[b * OUT + t] = acc2;
    }
}

// ---------------- launch ----------------
extern "C" void kernel_launch(void* const* d_in, const int* in_sizes, int n_in,
                              void* d_out, int out_size)
{
    const float* x      = (const float*)d_in[0];
    const float* r0     = (const float*)d_in[1];
    const float* sr0    = (const float*)d_in[2];
    const float* si0    = (const float*)d_in[3];
    const float* w_r0   = (const float*)d_in[4];
    const float* w_w0   = (const float*)d_in[5];
    const float* mem    = (const float*)d_in[6];
    const float* encW   = (const float*)d_in[7];
    const float* encb   = (const float*)d_in[8];
    const float* log_dt = (const float*)d_in[9];
    const float* logAr  = (const float*)d_in[10];
    const float* Aim    = (const float*)d_in[11];
    const float* Cre    = (const float*)d_in[12];
    const float* Cim    = (const float*)d_in[13];
    const float* Dv     = (const float*)d_in[14];
    const float* decW   = (const float*)d_in[15];
    const float* decb   = (const float*)d_in[16];
    const float* readW  = (const float*)d_in[17];
    const float* readb  = (const float*)d_in[18];
    const float* writeW = (const float*)d_in[19];
    const float* writeb = (const float*)d_in[20];
    float* out = (float*)d_out;

    k_encode_scan<<<dim3(B, H / 16), 256>>>(x, r0, sr0, si0, encW, encb,
                                            log_dt, logAr, Aim, Cre, Cim, Dv,
                                            writeW, writeb, readW, readb);
    k_pass1_addr<<<512, 256>>>(mem, w_w0, w_r0);
    k_readvec_dec<<<dim3(B, 32), 256>>>(mem, decW, decb, out);
}

// round 10
// speedup vs baseline: 1.0850x; 1.0850x over previous
#include <cuda_runtime.h>
#include <math.h>

#define B 32
#define L 256
#define EXT 64
#define H 256
#define M 64
#define NMEM 4096
#define NST 32
#define OUT 64

typedef unsigned long long ull;

// ---------------- scratch (device globals; no allocation) ----------------
__device__ float g_xm[B * H];
__device__ float g_kw[B * M], g_e[B * M], g_a[B * M], g_kr[B * M];
__device__ float g_pw[B * 8], g_pr[B * 8];
__device__ float g_score[B * NMEM];
__device__ float g_st[7][B * NMEM];    // d1,d2,ss,s2,s3,s4,s5
__device__ float g_ww[B * NMEM], g_wr[B * NMEM];
__device__ float g_rpart[B * 32 * M];
__device__ __align__(16) float g_part[(size_t)B * H * 256];  // [hid][c][re32|im32]
__device__ float g_usum[B * H * 4];

// ---------------- helpers ----------------
__device__ __forceinline__ float wredsum(float v) {
    #pragma unroll
    for (int o = 16; o > 0; o >>= 1) v += __shfl_xor_sync(0xffffffffu, v, o);
    return v;
}
__device__ __forceinline__ float gredsum16(float v) {
    #pragma unroll
    for (int o = 8; o > 0; o >>= 1) v += __shfl_xor_sync(0xffffffffu, v, o);
    return v;
}
__device__ __forceinline__ float wredmax(float v) {
    #pragma unroll
    for (int o = 16; o > 0; o >>= 1) v = fmaxf(v, __shfl_xor_sync(0xffffffffu, v, o));
    return v;
}
__device__ __forceinline__ float softplus_f(float x) {
    return (x > 20.f) ? x : log1pf(expf(x));
}
__device__ __forceinline__ float sigmoid_f(float x) {
    return 1.f / (1.f + expf(-x));
}
__device__ __forceinline__ ull pack2(float lo, float hi) {
    ull r; asm("mov.b64 %0,{%1,%2};" : "=l"(r) : "f"(lo), "f"(hi)); return r;
}
__device__ __forceinline__ void unpack2(ull v, float& lo, float& hi) {
    asm("mov.b64 {%0,%1},%2;" : "=f"(lo), "=f"(hi) : "l"(v));
}
__device__ __forceinline__ ull f2fma(ull a, ull b, ull c) {
    ull d; asm("fma.rn.f32x2 %0,%1,%2,%3;" : "=l"(d) : "l"(a), "l"(b), "l"(c)); return d;
}
__device__ __forceinline__ ull f2mul(ull a, ull b) {
    ull d; asm("mul.rn.f32x2 %0,%1,%2;" : "=l"(d) : "l"(a), "l"(b)); return d;
}

// ============ Kernel 1: one-chunk encoder GEMM + 64-step scan partial ============
// grid (B, H/16, 4 chunks), block 256; warp = 2 heads, 16-lane half packs 2 states/lane
__global__ void __launch_bounds__(256) k_encode4(
    const float* __restrict__ x, const float* __restrict__ r0,
    const float* __restrict__ encW, const float* __restrict__ encb,
    const float* __restrict__ log_dt, const float* __restrict__ logAr,
    const float* __restrict__ Aim)
{
    __shared__ float xsT[64 * 66];
    __shared__ ull   Wd[128 * 16];
    __shared__ ull   us2[16 * 64];

    int b = blockIdx.x, hg = blockIdx.y, c = blockIdx.z;
    int t = threadIdx.x, w = t >> 5, lane = t & 31;
    int sel = lane >> 4, p = lane & 15;
    int slot = w * 2 + sel;
    int h = hg * 16 + slot;

    for (int i = t; i < 128 * 16; i += 256) {
        int e = i >> 4, sl = i & 15;
        float wv = encW[e * H + hg * 16 + sl];
        Wd[i] = pack2(wv, wv);
    }
    {
        int l0 = c * 64;
        for (int i = t; i < 64 * 64; i += 256) {
            int rr = i >> 6, cc = i & 63;
            xsT[cc * 66 + rr] = x[((b * L) + (l0 + rr)) * EXT + cc];
        }
    }
    __syncthreads();

    // effective bias
    float cb = 0.f;
    #pragma unroll
    for (int m = p; m < M; m += 16) {
        float lo, hi; unpack2(Wd[(EXT + m) * 16 + slot], lo, hi);
        cb += r0[b * M + m] * lo;
    }
    cb = gredsum16(cb) + encb[h];
    ull cdup = pack2(cb, cb);

    // per-lane S4D constants (2 states)
    int n0 = 2 * p;
    float dt = expf(log_dt[h]);
    float ar_s[2], ai_s[2], dAr_s[2], dAi_s[2];
    #pragma unroll
    for (int s = 0; s < 2; s++) {
        int idx = h * NST + n0 + s;
        ar_s[s] = -expf(logAr[idx]);
        ai_s[s] = Aim[idx];
        float er = expf(dt * ar_s[s]);
        dAr_s[s] = er * cosf(dt * ai_s[s]);
        dAi_s[s] = er * sinf(dt * ai_s[s]);
    }
    ull dAr2  = pack2(dAr_s[0], dAr_s[1]);
    ull dAi2  = pack2(dAi_s[0], dAi_s[1]);
    ull ndAi2 = pack2(-dAi_s[0], -dAi_s[1]);

    int base = slot * 64;
    float usum = 0.f;

    // GEMM: u for this chunk's 64 l's
    {
        ull acc0 = cdup, acc1 = cdup;
        #pragma unroll
        for (int e = 0; e < EXT; e++) {
            ull wv = Wd[e * 16 + slot];
            acc0 = f2fma(wv, *(const ull*)&xsT[e * 66 + 2 * p], acc0);
            acc1 = f2fma(wv, *(const ull*)&xsT[e * 66 + 2 * (p + 16)], acc1);
        }
        float u0, u1; unpack2(acc0, u0, u1);
        us2[base + 2 * p]     = pack2(u0, u0);
        us2[base + 2 * p + 1] = pack2(u1, u1);
        usum += u0 + u1;
        unpack2(acc1, u0, u1);
        us2[base + 2 * (p + 16)]     = pack2(u0, u0);
        us2[base + 2 * (p + 16) + 1] = pack2(u1, u1);
        usum += u0 + u1;
    }
    __syncwarp();

    // 64-step scan: t <- dA*t + u
    ull tr2 = 0, ti2 = 0;
    #pragma unroll 8
    for (int j = 0; j < 64; j++) {
        ull u2 = us2[base + j];
        ull tA = f2fma(ndAi2, ti2, u2);
        ull trn = f2fma(dAr2, tr2, tA);
        ull tB = f2mul(dAr2, ti2);
        ti2 = f2fma(dAi2, tr2, tB);
        tr2 = trn;
    }

    // pre-multiply by dA^(64*(3-c)) and write partials
    usum = gredsum16(usum);
    float Trp[2], Tip[2];
    unpack2(tr2, Trp[0], Trp[1]);
    unpack2(ti2, Tip[0], Tip[1]);
    float k = 64.f * (float)(3 - c);
    int hid = b * H + h;
    float pr[2], pi[2];
    #pragma unroll
    for (int s = 0; s < 2; s++) {
        float epr = expf(k * dt * ar_s[s]);
        float ang = k * dt * ai_s[s];
        float cpr = epr * cosf(ang);
        float cpi = epr * sinf(ang);
        pr[s] = cpr * Trp[s] - cpi * Tip[s];
        pi[s] = cpi * Trp[s] + cpr * Tip[s];
    }
    size_t obase = (size_t)hid * 256 + c * 64;
    *(float2*)&g_part[obase + n0]      = make_float2(pr[0], pr[1]);
    *(float2*)&g_part[obase + 32 + n0] = make_float2(pi[0], pi[1]);
    if (p == 0) g_usum[hid * 4 + c] = usum;
}

// ============ Kernel 1b: combine 4 chunk partials -> xm ============
// grid (B, H/8), block 256; warp = 1 head, lane = state
__global__ void __launch_bounds__(256) k_combine(
    const float* __restrict__ sr0, const float* __restrict__ si0,
    const float* __restrict__ log_dt, const float* __restrict__ logAr,
    const float* __restrict__ Aim, const float* __restrict__ Cre,
    const float* __restrict__ Cim, const float* __restrict__ Dv)
{
    int b = blockIdx.x;
    int w = threadIdx.x >> 5, n = threadIdx.x & 31;
    int h = blockIdx.y * 8 + w;
    int hid = b * H + h;
    size_t base = (size_t)hid * 256;

    float Tr = 0.f, Ti = 0.f;
    #pragma unroll
    for (int c = 0; c < 4; c++) {
        Tr += g_part[base + c * 64 + n];
        Ti += g_part[base + c * 64 + 32 + n];
    }
    float usum = g_usum[hid * 4 + 0] + g_usum[hid * 4 + 1]
               + g_usum[hid * 4 + 2] + g_usum[hid * 4 + 3];

    int idx = h * NST + n;
    float dt = expf(log_dt[h]);
    float ar = -expf(logAr[idx]);
    float ai = Aim[idx];
    float er = expf(dt * ar);
    float dar = er * cosf(dt * ai);
    float dai = er * sinf(dt * ai);

    float xr = dar * Tr - dai * Ti;
    float xi = dai * Tr + dar * Ti;
    float wr = usum - xr, wi = -xi;
    float den = ar * ar + ai * ai;
    float invr = -ar / den, invi = ai / den;
    float Sr = invr * wr - invi * wi;
    float Si = invr * wi + invi * wr;

    float s0r = sr0[b * H * NST + idx], s0i = si0[b * H * NST + idx];
    if (s0r != 0.f || s0i != 0.f) {
        float eL = expf((float)L * dt * ar);
        float phi = (float)L * dt * ai;
        float dALr = eL * cosf(phi), dALi = eL * sinf(phi);
        float numr = 1.f - dALr, numi = -dALi;
        float omr = 1.f - dar, omi = -dai;
        float r2 = omr * omr + omi * omi;
        float qr = (numr * omr + numi * omi) / r2;
        float qi = (numi * omr - numr * omi) / r2;
        float gr = dar * qr - dai * qi;
        float gi = dai * qr + dar * qi;
        Sr += gr * s0r - gi * s0i;
        Si += gr * s0i + gi * s0r;
    }

    float val = Cre[idx] * Sr - Cim[idx] * Si;
    val = wredsum(val);
    if (n == 0)
        g_xm[hid] = (2.f * val + (Dv[h] + 1.f) * usum) * (1.f / (float)L);
}

// ============ Kernel 2: head projections + per-batch consts ============
__global__ void k_heads(
    const float* __restrict__ writeW, const float* __restrict__ writeb,
    const float* __restrict__ readW,  const float* __restrict__ readb)
{
    __shared__ float xs[H];
    __shared__ float sow[3 * M + 6];
    __shared__ float sorh[M + 6];
    int b = blockIdx.x, t = threadIdx.x;
    if (t < H) xs[t] = g_xm[b * H + t];
    __syncthreads();

    if (t < 198) {
        float acc = writeb[t];
        for (int hh = 0; hh < H; hh++) acc = fmaf(xs[hh], writeW[hh * 198 + t], acc);
        sow[t] = acc;
    } else if (t < 268) {
        int j = t - 198;
        float acc = readb[j];
        for (int hh = 0; hh < H; hh++) acc = fmaf(xs[hh], readW[hh * 70 + j], acc);
        sorh[j] = acc;
    }
    __syncthreads();

    if (t < M) {
        g_kw[b * M + t] = sow[t];
        g_e[b * M + t]  = sigmoid_f(sow[M + 6 + t]);
        g_a[b * M + t]  = sow[2 * M + 6 + t];
        g_kr[b * M + t] = sorh[t];
    } else if (t == M) {
        float beta = softplus_f(sow[M]);
        float g    = sigmoid_f(sow[M + 1]);
        float m3 = fmaxf(sow[M + 2], fmaxf(sow[M + 3], sow[M + 4]));
        float e0 = expf(sow[M + 2] - m3), e1 = expf(sow[M + 3] - m3), e2 = expf(sow[M + 4] - m3);
        float Z = e0 + e1 + e2;
        float gamma = 1.f + softplus_f(sow[M + 5]);
        float nk = 0.f;
        for (int m = 0; m < M; m++) { float v = sow[m]; nk += v * v; }
        g_pw[b * 8 + 0] = beta; g_pw[b * 8 + 1] = g;
        g_pw[b * 8 + 2] = e0 / Z; g_pw[b * 8 + 3] = e1 / Z; g_pw[b * 8 + 4] = e2 / Z;
        g_pw[b * 8 + 5] = gamma; g_pw[b * 8 + 6] = sqrtf(nk);
    } else if (t == M + 1) {
        float beta = softplus_f(sorh[M]);
        float g    = sigmoid_f(sorh[M + 1]);
        float m3 = fmaxf(sorh[M + 2], fmaxf(sorh[M + 3], sorh[M + 4]));
        float e0 = expf(sorh[M + 2] - m3), e1 = expf(sorh[M + 3] - m3), e2 = expf(sorh[M + 4] - m3);
        float Z = e0 + e1 + e2;
        float gamma = 1.f + softplus_f(sorh[M + 5]);
        float nk = 0.f;
        for (int m = 0; m < M; m++) { float v = sorh[m]; nk += v * v; }
        g_pr[b * 8 + 0] = beta; g_pr[b * 8 + 1] = g;
        g_pr[b * 8 + 2] = e0 / Z; g_pr[b * 8 + 3] = e1 / Z; g_pr[b * 8 + 4] = e2 / Z;
        g_pr[b * 8 + 5] = gamma; g_pr[b * 8 + 6] = sqrtf(nk);
    } else if (t == M + 2) {
        float akr = 0.f, aa = 0.f;
        for (int m = 0; m < M; m++) {
            float av = sow[2 * M + 6 + m];
            akr = fmaf(av, sorh[m], akr);
            aa  = fmaf(av, av, aa);
        }
        g_pr[b * 8 + 7] = akr;
        g_pw[b * 8 + 7] = aa;
    }
}

// ============ Kernel 3: single mem pass -> write score + 7 read-stats ============
__global__ void __launch_bounds__(256) k_pass1(const float* __restrict__ mem)
{
    __shared__ float kw[M], kr_[M], ekr[M], ev[M], e2v[M], av[M], eav[M];
    int t = threadIdx.x;
    int b = blockIdx.x >> 4;
    int row = blockIdx.x * 256 + t;

    if (t < M) {
        float kwv = g_kw[b * M + t];
        float krv = g_kr[b * M + t];
        float e_  = g_e[b * M + t];
        float a_  = g_a[b * M + t];
        kw[t] = kwv; kr_[t] = krv; ekr[t] = e_ * krv;
        ev[t] = e_; e2v[t] = e_ * e_; av[t] = a_; eav[t] = e_ * a_;
    }
    __syncthreads();

    const float4* mp = (const float4*)(mem + (size_t)row * M);
    float dw = 0.f, ss = 0.f, d1 = 0.f, d2 = 0.f, s2 = 0.f, s3 = 0.f, s4 = 0.f, s5 = 0.f;
    #pragma unroll
    for (int i = 0; i < 16; i++) {
        float4 v = mp[i];
        int m = i * 4;
        #pragma unroll
        for (int j = 0; j < 4; j++) {
            float vv = (&v.x)[j];
            int mm = m + j;
            float v2 = vv * vv;
            dw = fmaf(vv, kw[mm],  dw);
            ss += v2;
            d1 = fmaf(vv, kr_[mm], d1);
            d2 = fmaf(vv, ekr[mm], d2);
            s2 = fmaf(v2, ev[mm],  s2);
            s3 = fmaf(v2, e2v[mm], s3);
            s4 = fmaf(vv, av[mm],  s4);
            s5 = fmaf(vv, eav[mm], s5);
        }
    }
    float beta = g_pw[b * 8 + 0], knw = g_pw[b * 8 + 6];
    g_score[row] = beta * dw / (sqrtf(ss) * knw + 1e-16f);
    g_st[0][row] = d1; g_st[1][row] = d2; g_st[2][row] = ss;
    g_st[3][row] = s2; g_st[4][row] = s3; g_st[5][row] = s4; g_st[6][row] = s5;
}

// ============ Kernel 4: write addressing + read score + read addressing ============
__global__ void __launch_bounds__(1024) k_addr2(
    const float* __restrict__ ww0, const float* __restrict__ wr0)
{
    __shared__ float sc[NMEM];
    __shared__ float wg[NMEM];
    __shared__ float red[32];
    __shared__ float bcast;
    int b = blockIdx.x, t = threadIdx.x;
    int lane = t & 31, w = t >> 5;

    // phase A: write addressing
    {
        float g = g_pw[b * 8 + 1], s0 = g_pw[b * 8 + 2], s1 = g_pw[b * 8 + 3];
        float s2 = g_pw[b * 8 + 4], gamma = g_pw[b * 8 + 5];

        float lm = __int_as_float(0xff800000);
        #pragma unroll
        for (int i = 0; i < 4; i++) {
            int n = t + 1024 * i;
            float v = g_score[b * NMEM + n];
            sc[n] = v; lm = fmaxf(lm, v);
        }
        lm = wredmax(lm);
        if (lane == 0) red[w] = lm;
        __syncthreads();
        if (w == 0) { float v = red[lane]; v = wredmax(v); if (lane == 0) bcast = v; }
        __syncthreads();
        float bm = bcast;

        float ls = 0.f;
        #pragma unroll
        for (int i = 0; i < 4; i++) {
            int n = t + 1024 * i;
            float pv = __expf(sc[n] - bm);
            sc[n] = pv; ls += pv;
        }
        ls = wredsum(ls);
        if (lane == 0) red[w] = ls;
        __syncthreads();
        if (w == 0) { float v = red[lane]; v = wredsum(v); if (lane == 0) bcast = v; }
        __syncthreads();
        float gZ = g / bcast, og = 1.f - g;

        #pragma unroll
        for (int i = 0; i < 4; i++) {
            int n = t + 1024 * i;
            wg[n] = fmaf(gZ, sc[n], og * ww0[b * NMEM + n]);
        }
        __syncthreads();

        float lp = 0.f;
        #pragma unroll
        for (int i = 0; i < 4; i++) {
            int n = t + 1024 * i;
            float wt = s0 * wg[(n - 1) & (NMEM - 1)] + s1 * wg[n] + s2 * wg[(n + 1) & (NMEM - 1)];
            float wp = (wt > 0.f) ? __powf(wt, gamma) : 0.f;
            sc[n] = wp; lp += wp;
        }
        lp = wredsum(lp);
        if (lane == 0) red[w] = lp;
        __syncthreads();
        if (w == 0) { float v = red[lane]; v = wredsum(v); if (lane == 0) bcast = v + 1e-16f; }
        __syncthreads();
        float iZp = 1.f / bcast;

        #pragma unroll
        for (int i = 0; i < 4; i++) {
            int n = t + 1024 * i;
            g_ww[b * NMEM + n] = sc[n] * iZp;
        }
        __syncthreads();
    }

    // phase B: read score from stats + read addressing
    {
        float beta = g_pr[b * 8 + 0], knr = g_pr[b * 8 + 6];
        float akr  = g_pr[b * 8 + 7], aa  = g_pw[b * 8 + 7];
        float g = g_pr[b * 8 + 1], s0 = g_pr[b * 8 + 2], s1 = g_pr[b * 8 + 3];
        float s2p = g_pr[b * 8 + 4], gamma = g_pr[b * 8 + 5];

        float lm = __int_as_float(0xff800000);
        #pragma unroll
        for (int i = 0; i < 4; i++) {
            int n = t + 1024 * i;
            int row = b * NMEM + n;
            float wwv = g_ww[row];
            float d1 = g_st[0][row], d2 = g_st[1][row], ssv = g_st[2][row];
            float s2v = g_st[3][row], s3v = g_st[4][row], s4v = g_st[5][row], s5v = g_st[6][row];
            float dot = d1 - wwv * (d2 - akr);
            float n2 = ssv + wwv * (2.f * (s4v - s2v)) + wwv * wwv * (s3v - 2.f * s5v + aa);
            float v = beta * dot / (sqrtf(fmaxf(n2, 0.f)) * knr + 1e-16f);
            sc[n] = v; lm = fmaxf(lm, v);
        }
        lm = wredmax(lm);
        if (lane == 0) red[w] = lm;
        __syncthreads();
        if (w == 0) { float v = red[lane]; v = wredmax(v); if (lane == 0) bcast = v; }
        __syncthreads();
        float bm = bcast;

        float ls = 0.f;
        #pragma unroll
        for (int i = 0; i < 4; i++) {
            int n = t + 1024 * i;
            float pv = __expf(sc[n] - bm);
            sc[n] = pv; ls += pv;
        }
        ls = wredsum(ls);
        if (lane == 0) red[w] = ls;
        __syncthreads();
        if (w == 0) { float v = red[lane]; v = wredsum(v); if (lane == 0) bcast = v; }
        __syncthreads();
        float gZ = g / bcast, og = 1.f - g;

        #pragma unroll
        for (int i = 0; i < 4; i++) {
            int n = t + 1024 * i;
            wg[n] = fmaf(gZ, sc[n], og * wr0[b * NMEM + n]);
        }
        __syncthreads();

        float lp = 0.f;
        #pragma unroll
        for (int i = 0; i < 4; i++) {
            int n = t + 1024 * i;
            float wt = s0 * wg[(n - 1) & (NMEM - 1)] + s1 * wg[n] + s2p * wg[(n + 1) & (NMEM - 1)];
            float wp = (wt > 0.f) ? __powf(wt, gamma) : 0.f;
            sc[n] = wp; lp += wp;
        }
        lp = wredsum(lp);
        if (lane == 0) red[w] = lp;
        __syncthreads();
        if (w == 0) { float v = red[lane]; v = wredsum(v); if (lane == 0) bcast = v + 1e-16f; }
        __syncthreads();
        float iZp = 1.f / bcast;

        #pragma unroll
        for (int i = 0; i < 4; i++) {
            int n = t + 1024 * i;
            g_wr[b * NMEM + n] = sc[n] * iZp;
        }
    }
}

// ============ Kernel 5: r partials = w_r . mem2 ============
__global__ void __launch_bounds__(256) k_readvec(const float* __restrict__ mem)
{
    __shared__ float es4[M], as4[M];
    __shared__ float part[16][M + 4];
    int b = blockIdx.x, chunk = blockIdx.y;
    int t = threadIdx.x;
    int m4 = t & 15;
    int rgrp = t >> 4;
    if (t < M) { es4[t] = g_e[b * M + t]; as4[t] = g_a[b * M + t]; }
    __syncthreads();

    int m = m4 * 4;
    float4 ev = make_float4(es4[m], es4[m + 1], es4[m + 2], es4[m + 3]);
    float4 av = make_float4(as4[m], as4[m + 1], as4[m + 2], as4[m + 3]);

    float4 acc = make_float4(0.f, 0.f, 0.f, 0.f);
    int n0 = chunk * 128;
    #pragma unroll
    for (int k = 0; k < 8; k++) {
        int n = n0 + rgrp + 16 * k;
        int row = b * NMEM + n;
        float wwv = g_ww[row], wrv = g_wr[row];
        float4 v = *(const float4*)(mem + (size_t)row * M + m);
        float4 v2;
        v2.x = fmaf(v.x, 1.f - wwv * ev.x, wwv * av.x);
        v2.y = fmaf(v.y, 1.f - wwv * ev.y, wwv * av.y);
        v2.z = fmaf(v.z, 1.f - wwv * ev.z, wwv * av.z);
        v2.w = fmaf(v.w, 1.f - wwv * ev.w, wwv * av.w);
        acc.x = fmaf(wrv, v2.x, acc.x);
        acc.y = fmaf(wrv, v2.y, acc.y);
        acc.z = fmaf(wrv, v2.z, acc.z);
        acc.w = fmaf(wrv, v2.w, acc.w);
    }
    *(float4*)&part[rgrp][m] = acc;
    __syncthreads();

    if (t < M) {
        float s = 0.f;
        #pragma unroll
        for (int r = 0; r < 16; r++) s += part[r][t];
        g_rpart[(b * 32 + chunk) * M + t] = s;
    }
}

// ============ Kernel 6: decoder ============
__global__ void k_decode(const float* __restrict__ decW, const float* __restrict__ decb,
                         float* __restrict__ out)
{
    __shared__ float xs[H];
    __shared__ float rs[M];
    int b = blockIdx.x, t = threadIdx.x;
    xs[t] = g_xm[b * H + t];
    if (t < M) {
        float s = 0.f;
        #pragma unroll
        for (int c = 0; c < 32; c++) s += g_rpart[(b * 32 + c) * M + t];
        rs[t] = s;
    }
    __syncthreads();
    if (t < OUT) {
        float acc = decb[t];
        for (int hh = 0; hh < H; hh++) acc = fmaf(xs[hh], decW[hh * OUT + t], acc);
        for (int m = 0; m < M; m++) acc = fmaf(rs[m], decW[(H + m) * OUT + t], acc);
        out[b * OUT + t] = acc;
    }
}

// ---------------- launch ----------------
extern "C" void kernel_launch(void* const* d_in, const int* in_sizes, int n_in,
                              void* d_out, int out_size)
{
    const float* x      = (const float*)d_in[0];
    const float* r0     = (const float*)d_in[1];
    const float* sr0    = (const float*)d_in[2];
    const float* si0    = (const float*)d_in[3];
    const float* w_r0   = (const float*)d_in[4];
    const float* w_w0   = (const float*)d_in[5];
    const float* mem    = (const float*)d_in[6];
    const float* encW   = (const float*)d_in[7];
    const float* encb   = (const float*)d_in[8];
    const float* log_dt = (const float*)d_in[9];
    const float* logAr  = (const float*)d_in[10];
    const float* Aim    = (const float*)d_in[11];
    const float* Cre    = (const float*)d_in[12];
    const float* Cim    = (const float*)d_in[13];
    const float* Dv     = (const float*)d_in[14];
    const float* decW   = (const float*)d_in[15];
    const float* decb   = (const float*)d_in[16];
    const float* readW  = (const float*)d_in[17];
    const float* readb  = (const float*)d_in[18];
    const float* writeW = (const float*)d_in[19];
    const float* writeb = (const float*)d_in[20];
    float* out = (float*)d_out;

    k_encode4<<<dim3(B, H / 16, 4), 256>>>(x, r0, encW, encb, log_dt, logAr, Aim);
    k_combine<<<dim3(B, H / 8), 256>>>(sr0, si0, log_dt, logAr, Aim, Cre, Cim, Dv);
    k_heads<<<B, 288>>>(writeW, writeb, readW, readb);
    k_pass1<<<512, 256>>>(mem);
    k_addr2<<<B, 1024>>>(w_w0, w_r0);
    k_readvec<<<dim3(B, 32), 256>>>(mem);
    k_decode<<<B, 256>>>(decW, decb, out);
}

// round 11
// speedup vs baseline: 1.1283x; 1.0399x over previous
#include <cuda_runtime.h>
#include <math.h>

#define B 32
#define L 256
#define EXT 64
#define H 256
#define M 64
#define NMEM 4096
#define NST 32
#define OUT 64

typedef unsigned long long ull;

// ---------------- scratch (device globals; no allocation) ----------------
__device__ float g_xm[B * H];
__device__ float g_kw[B * M], g_e[B * M], g_a[B * M], g_kr[B * M];
__device__ float g_pw[B * 8], g_pr[B * 8];
__device__ float g_score[B * NMEM];
__device__ float g_st[7][B * NMEM];    // d1,d2,ss,s2,s3,s4,s5
__device__ float g_ww[B * NMEM], g_wr[B * NMEM];
__device__ float g_rpart[B * 32 * M];

// ---------------- helpers ----------------
__device__ __forceinline__ float wredsum(float v) {
    #pragma unroll
    for (int o = 16; o > 0; o >>= 1) v += __shfl_xor_sync(0xffffffffu, v, o);
    return v;
}
__device__ __forceinline__ float gredsum16(float v) {
    #pragma unroll
    for (int o = 8; o > 0; o >>= 1) v += __shfl_xor_sync(0xffffffffu, v, o);
    return v;
}
__device__ __forceinline__ float wredmax(float v) {
    #pragma unroll
    for (int o = 16; o > 0; o >>= 1) v = fmaxf(v, __shfl_xor_sync(0xffffffffu, v, o));
    return v;
}
__device__ __forceinline__ float softplus_f(float x) {
    return (x > 20.f) ? x : log1pf(expf(x));
}
__device__ __forceinline__ float sigmoid_f(float x) {
    return 1.f / (1.f + expf(-x));
}
__device__ __forceinline__ ull pack2(float lo, float hi) {
    ull r; asm("mov.b64 %0,{%1,%2};" : "=l"(r) : "f"(lo), "f"(hi)); return r;
}
__device__ __forceinline__ void unpack2(ull v, float& lo, float& hi) {
    asm("mov.b64 {%0,%1},%2;" : "=f"(lo), "=f"(hi) : "l"(v));
}
__device__ __forceinline__ ull f2fma(ull a, ull b, ull c) {
    ull d; asm("fma.rn.f32x2 %0,%1,%2,%3;" : "=l"(d) : "l"(a), "l"(b), "l"(c)); return d;
}
__device__ __forceinline__ ull f2mul(ull a, ull b) {
    ull d; asm("mul.rn.f32x2 %0,%1,%2;" : "=l"(d) : "l"(a), "l"(b)); return d;
}

// ============ Kernel 1: encoder GEMM + S4D, 4-chunk ILP scan in-lane ============
// grid (B, H/16), block 256. Warp = 2 heads; each 16-lane half packs 2 states/lane.
__global__ void __launch_bounds__(256) k_encode_scan(
    const float* __restrict__ x, const float* __restrict__ r0,
    const float* __restrict__ sr0, const float* __restrict__ si0,
    const float* __restrict__ encW, const float* __restrict__ encb,
    const float* __restrict__ log_dt, const float* __restrict__ logAr,
    const float* __restrict__ Aim, const float* __restrict__ Cre,
    const float* __restrict__ Cim, const float* __restrict__ Dv)
{
    __shared__ float xsT[64 * 66];     // [e][l] stride 66 (8B-aligned ull reads)
    __shared__ ull   Wd[EXT * 16];     // encoder weights (EXT rows only), duplicated
    __shared__ float us[16 * 256];     // all 256 u's per head slot

    int b = blockIdx.x, hg = blockIdx.y;
    int t = threadIdx.x, w = t >> 5, lane = t & 31;
    int sel = lane >> 4, p = lane & 15;
    int slot = w * 2 + sel;
    int h = hg * 16 + slot;

    for (int i = t; i < EXT * 16; i += 256) {
        int e = i >> 4, sl = i & 15;
        float wv = encW[e * H + hg * 16 + sl];
        Wd[i] = pack2(wv, wv);
    }

    // effective bias: enc_b[h] + r0 . enc_W[EXT:,h] (direct gmem, tiny)
    float cb = 0.f;
    #pragma unroll
    for (int m = p; m < M; m += 16)
        cb = fmaf(r0[b * M + m], encW[(EXT + m) * H + h], cb);
    cb = gredsum16(cb) + encb[h];
    ull cdup = pack2(cb, cb);

    // per-lane S4D constants (2 states: n0, n0+1)
    int n0 = 2 * p;
    float dt = expf(log_dt[h]);
    float ar_s[2], ai_s[2], dAr_s[2], dAi_s[2];
    #pragma unroll
    for (int s = 0; s < 2; s++) {
        int idx = h * NST + n0 + s;
        ar_s[s] = -expf(logAr[idx]);
        ai_s[s] = Aim[idx];
        float er = expf(dt * ar_s[s]);
        dAr_s[s] = er * cosf(dt * ai_s[s]);
        dAi_s[s] = er * sinf(dt * ai_s[s]);
    }
    ull dAr2  = pack2(dAr_s[0], dAr_s[1]);
    ull dAi2  = pack2(dAi_s[0], dAi_s[1]);
    ull ndAi2 = pack2(-dAi_s[0], -dAi_s[1]);

    float usum = 0.f;
    int ub = slot * 256;

    // ---- GEMM all 4 chunks into us ----
    for (int ch = 0; ch < 4; ch++) {
        __syncthreads();
        int l0 = ch * 64;
        for (int i = t; i < 64 * 64; i += 256) {
            int rr = i >> 6, cc = i & 63;
            xsT[cc * 66 + rr] = x[((b * L) + (l0 + rr)) * EXT + cc];
        }
        __syncthreads();

        ull acc0 = cdup, acc1 = cdup;
        #pragma unroll
        for (int e = 0; e < EXT; e++) {
            ull wv = Wd[e * 16 + slot];
            acc0 = f2fma(wv, *(const ull*)&xsT[e * 66 + 2 * p], acc0);
            acc1 = f2fma(wv, *(const ull*)&xsT[e * 66 + 2 * (p + 16)], acc1);
        }
        float u0, u1;
        unpack2(acc0, u0, u1);
        us[ub + ch * 64 + 2 * p]     = u0;
        us[ub + ch * 64 + 2 * p + 1] = u1;
        usum += u0 + u1;
        unpack2(acc1, u0, u1);
        us[ub + ch * 64 + 2 * (p + 16)]     = u0;
        us[ub + ch * 64 + 2 * (p + 16) + 1] = u1;
        usum += u0 + u1;
    }
    __syncthreads();

    // ---- 4-chunk ILP scan: 4 independent accumulators per lane ----
    ull tr[4] = {0, 0, 0, 0}, ti[4] = {0, 0, 0, 0};
    #pragma unroll 4
    for (int j = 0; j < 64; j++) {
        #pragma unroll
        for (int c = 0; c < 4; c++) {
            float uv = us[ub + c * 64 + j];
            ull u2 = pack2(uv, uv);
            ull tA = f2fma(ndAi2, ti[c], u2);
            ull trn = f2fma(dAr2, tr[c], tA);
            ull tB = f2mul(dAr2, ti[c]);
            ti[c] = f2fma(dAi2, tr[c], tB);
            tr[c] = trn;
        }
    }

    // ---- combine chunks in-lane: T = T3 + P*T2 + P^2*T1 + P^3*T0, P = dA^64 ----
    usum = gredsum16(usum);
    float Trs[2], Tis[2];
    #pragma unroll
    for (int s = 0; s < 2; s++) {
        float e64 = expf(64.f * dt * ar_s[s]);
        float ang = 64.f * dt * ai_s[s];
        float Prr = e64 * cosf(ang), Pii = e64 * sinf(ang);
        // powers
        float W2r = Prr, W2i = Pii;
        float W1r = Prr * Prr - Pii * Pii, W1i = 2.f * Prr * Pii;
        float W0r = W1r * Prr - W1i * Pii, W0i = W1i * Prr + W1r * Pii;
        float t3r, t3i, t2r, t2i, t1r, t1i, t0r, t0i, dum;
        if (s == 0) {
            unpack2(tr[3], t3r, dum); unpack2(ti[3], t3i, dum);
            unpack2(tr[2], t2r, dum); unpack2(ti[2], t2i, dum);
            unpack2(tr[1], t1r, dum); unpack2(ti[1], t1i, dum);
            unpack2(tr[0], t0r, dum); unpack2(ti[0], t0i, dum);
        } else {
            unpack2(tr[3], dum, t3r); unpack2(ti[3], dum, t3i);
            unpack2(tr[2], dum, t2r); unpack2(ti[2], dum, t2i);
            unpack2(tr[1], dum, t1r); unpack2(ti[1], dum, t1i);
            unpack2(tr[0], dum, t0r); unpack2(ti[0], dum, t0i);
        }
        float Tr = t3r + (W2r * t2r - W2i * t2i) + (W1r * t1r - W1i * t1i) + (W0r * t0r - W0i * t0i);
        float Ti = t3i + (W2i * t2r + W2r * t2i) + (W1i * t1r + W1r * t1i) + (W0i * t0r + W0r * t0i);
        Trs[s] = Tr; Tis[s] = Ti;
    }

    // ---- closed form: sum_l s_l = Geo*s0 + (-1/A)*(sum_u - dA*T) ----
    float val = 0.f;
    #pragma unroll
    for (int s = 0; s < 2; s++) {
        int idx = h * NST + n0 + s;
        float ar = ar_s[s], ai = ai_s[s];
        float dar = dAr_s[s], dai = dAi_s[s];
        float xr = dar * Trs[s] - dai * Tis[s];
        float xi = dai * Trs[s] + dar * Tis[s];
        float wr = usum - xr, wi = -xi;
        float den = ar * ar + ai * ai;
        float invr = -ar / den, invi = ai / den;
        float Sr = invr * wr - invi * wi;
        float Si = invr * wi + invi * wr;
        float s0r = sr0[b * H * NST + idx], s0i = si0[b * H * NST + idx];
        if (s0r != 0.f || s0i != 0.f) {
            float eL = expf((float)L * dt * ar);
            float phi = (float)L * dt * ai;
            float dALr = eL * cosf(phi), dALi = eL * sinf(phi);
            float numr = 1.f - dALr, numi = -dALi;
            float omr = 1.f - dar, omi = -dai;
            float r2 = omr * omr + omi * omi;
            float qr = (numr * omr + numi * omi) / r2;
            float qi = (numi * omr - numr * omi) / r2;
            float gr = dar * qr - dai * qi;
            float gi = dai * qr + dar * qi;
            Sr += gr * s0r - gi * s0i;
            Si += gr * s0i + gi * s0r;
        }
        val += Cre[idx] * Sr - Cim[idx] * Si;
    }
    val = gredsum16(val);
    if (p == 0)
        g_xm[b * H + h] = (2.f * val + (Dv[h] + 1.f) * usum) * (1.f / (float)L);
}

// ============ Kernel 2: head projections + per-batch consts ============
__global__ void k_heads(
    const float* __restrict__ writeW, const float* __restrict__ writeb,
    const float* __restrict__ readW,  const float* __restrict__ readb)
{
    __shared__ float xs[H];
    __shared__ float sow[3 * M + 6];
    __shared__ float sorh[M + 6];
    int b = blockIdx.x, t = threadIdx.x;
    if (t < H) xs[t] = g_xm[b * H + t];
    __syncthreads();

    if (t < 198) {
        float acc = writeb[t];
        for (int hh = 0; hh < H; hh++) acc = fmaf(xs[hh], writeW[hh * 198 + t], acc);
        sow[t] = acc;
    } else if (t < 268) {
        int j = t - 198;
        float acc = readb[j];
        for (int hh = 0; hh < H; hh++) acc = fmaf(xs[hh], readW[hh * 70 + j], acc);
        sorh[j] = acc;
    }
    __syncthreads();

    if (t < M) {
        g_kw[b * M + t] = sow[t];
        g_e[b * M + t]  = sigmoid_f(sow[M + 6 + t]);
        g_a[b * M + t]  = sow[2 * M + 6 + t];
        g_kr[b * M + t] = sorh[t];
    } else if (t == M) {
        float beta = softplus_f(sow[M]);
        float g    = sigmoid_f(sow[M + 1]);
        float m3 = fmaxf(sow[M + 2], fmaxf(sow[M + 3], sow[M + 4]));
        float e0 = expf(sow[M + 2] - m3), e1 = expf(sow[M + 3] - m3), e2 = expf(sow[M + 4] - m3);
        float Z = e0 + e1 + e2;
        float gamma = 1.f + softplus_f(sow[M + 5]);
        float nk = 0.f;
        for (int m = 0; m < M; m++) { float v = sow[m]; nk += v * v; }
        g_pw[b * 8 + 0] = beta; g_pw[b * 8 + 1] = g;
        g_pw[b * 8 + 2] = e0 / Z; g_pw[b * 8 + 3] = e1 / Z; g_pw[b * 8 + 4] = e2 / Z;
        g_pw[b * 8 + 5] = gamma; g_pw[b * 8 + 6] = sqrtf(nk);
    } else if (t == M + 1) {
        float beta = softplus_f(sorh[M]);
        float g    = sigmoid_f(sorh[M + 1]);
        float m3 = fmaxf(sorh[M + 2], fmaxf(sorh[M + 3], sorh[M + 4]));
        float e0 = expf(sorh[M + 2] - m3), e1 = expf(sorh[M + 3] - m3), e2 = expf(sorh[M + 4] - m3);
        float Z = e0 + e1 + e2;
        float gamma = 1.f + softplus_f(sorh[M + 5]);
        float nk = 0.f;
        for (int m = 0; m < M; m++) { float v = sorh[m]; nk += v * v; }
        g_pr[b * 8 + 0] = beta; g_pr[b * 8 + 1] = g;
        g_pr[b * 8 + 2] = e0 / Z; g_pr[b * 8 + 3] = e1 / Z; g_pr[b * 8 + 4] = e2 / Z;
        g_pr[b * 8 + 5] = gamma; g_pr[b * 8 + 6] = sqrtf(nk);
    } else if (t == M + 2) {
        float akr = 0.f, aa = 0.f;
        for (int m = 0; m < M; m++) {
            float av = sow[2 * M + 6 + m];
            akr = fmaf(av, sorh[m], akr);
            aa  = fmaf(av, av, aa);
        }
        g_pr[b * 8 + 7] = akr;
        g_pw[b * 8 + 7] = aa;
    }
}

// ============ Kernel 3: mem pass, 16 lanes per row (coalesced) ============
// grid 512 (16 blocks/batch), block 256 = 16 row-groups; each iterates 16 rows.
__global__ void __launch_bounds__(256) k_pass1(const float* __restrict__ mem)
{
    __shared__ __align__(16) float kw[M], kr_[M], ekr[M], ev[M], e2v[M], av[M], eav[M];
    int t = threadIdx.x;
    int lane = t & 31;
    int q = lane & 15;          // float4 index within row
    int grp = t >> 4;           // 0..15 row-group within block
    int b = blockIdx.x >> 4;

    if (t < M) {
        float kwv = g_kw[b * M + t];
        float krv = g_kr[b * M + t];
        float e_  = g_e[b * M + t];
        float a_  = g_a[b * M + t];
        kw[t] = kwv; kr_[t] = krv; ekr[t] = e_ * krv;
        ev[t] = e_; e2v[t] = e_ * e_; av[t] = a_; eav[t] = e_ * a_;
    }
    __syncthreads();

    // per-lane coefficient registers (4 elements: 4q..4q+3)
    float4 ckw = *(const float4*)&kw[4 * q];
    float4 ckr = *(const float4*)&kr_[4 * q];
    float4 cek = *(const float4*)&ekr[4 * q];
    float4 cev = *(const float4*)&ev[4 * q];
    float4 ce2 = *(const float4*)&e2v[4 * q];
    float4 cav = *(const float4*)&av[4 * q];
    float4 cea = *(const float4*)&eav[4 * q];

    float beta = g_pw[b * 8 + 0], knw = g_pw[b * 8 + 6];

    #pragma unroll 4
    for (int iter = 0; iter < 16; iter++) {
        int row = blockIdx.x * 256 + iter * 16 + grp;
        float4 v = *(const float4*)(mem + (size_t)row * M + 4 * q);

        float dw = v.x * ckw.x + v.y * ckw.y + v.z * ckw.z + v.w * ckw.w;
        float ss = v.x * v.x + v.y * v.y + v.z * v.z + v.w * v.w;
        float d1 = v.x * ckr.x + v.y * ckr.y + v.z * ckr.z + v.w * ckr.w;
        float d2 = v.x * cek.x + v.y * cek.y + v.z * cek.z + v.w * cek.w;
        float s2 = v.x * v.x * cev.x + v.y * v.y * cev.y + v.z * v.z * cev.z + v.w * v.w * cev.w;
        float s3 = v.x * v.x * ce2.x + v.y * v.y * ce2.y + v.z * v.z * ce2.z + v.w * v.w * ce2.w;
        float s4 = v.x * cav.x + v.y * cav.y + v.z * cav.z + v.w * cav.w;
        float s5 = v.x * cea.x + v.y * cea.y + v.z * cea.z + v.w * cea.w;

        #pragma unroll
        for (int o = 8; o > 0; o >>= 1) {
            dw += __shfl_xor_sync(0xffffffffu, dw, o);
            ss += __shfl_xor_sync(0xffffffffu, ss, o);
            d1 += __shfl_xor_sync(0xffffffffu, d1, o);
            d2 += __shfl_xor_sync(0xffffffffu, d2, o);
            s2 += __shfl_xor_sync(0xffffffffu, s2, o);
            s3 += __shfl_xor_sync(0xffffffffu, s3, o);
            s4 += __shfl_xor_sync(0xffffffffu, s4, o);
            s5 += __shfl_xor_sync(0xffffffffu, s5, o);
        }

        if (q == 0) {
            g_score[row] = beta * dw / (sqrtf(ss) * knw + 1e-16f);
            g_st[0][row] = d1; g_st[1][row] = d2; g_st[2][row] = ss;
            g_st[3][row] = s2; g_st[4][row] = s3; g_st[5][row] = s4; g_st[6][row] = s5;
        }
    }
}

// ============ Kernel 4: write addressing + read score + read addressing ============
__global__ void __launch_bounds__(1024) k_addr2(
    const float* __restrict__ ww0, const float* __restrict__ wr0)
{
    __shared__ float sc[NMEM];
    __shared__ float wg[NMEM];
    __shared__ float red[32];
    __shared__ float bcast;
    int b = blockIdx.x, t = threadIdx.x;
    int lane = t & 31, w = t >> 5;

    // phase A: write addressing
    {
        float g = g_pw[b * 8 + 1], s0 = g_pw[b * 8 + 2], s1 = g_pw[b * 8 + 3];
        float s2 = g_pw[b * 8 + 4], gamma = g_pw[b * 8 + 5];

        float lm = __int_as_float(0xff800000);
        #pragma unroll
        for (int i = 0; i < 4; i++) {
            int n = t + 1024 * i;
            float v = g_score[b * NMEM + n];
            sc[n] = v; lm = fmaxf(lm, v);
        }
        lm = wredmax(lm);
        if (lane == 0) red[w] = lm;
        __syncthreads();
        if (w == 0) { float v = red[lane]; v = wredmax(v); if (lane == 0) bcast = v; }
        __syncthreads();
        float bm = bcast;

        float ls = 0.f;
        #pragma unroll
        for (int i = 0; i < 4; i++) {
            int n = t + 1024 * i;
            float pv = __expf(sc[n] - bm);
            sc[n] = pv; ls += pv;
        }
        ls = wredsum(ls);
        if (lane == 0) red[w] = ls;
        __syncthreads();
        if (w == 0) { float v = red[lane]; v = wredsum(v); if (lane == 0) bcast = v; }
        __syncthreads();
        float gZ = g / bcast, og = 1.f - g;

        #pragma unroll
        for (int i = 0; i < 4; i++) {
            int n = t + 1024 * i;
            wg[n] = fmaf(gZ, sc[n], og * ww0[b * NMEM + n]);
        }
        __syncthreads();

        float lp = 0.f;
        #pragma unroll
        for (int i = 0; i < 4; i++) {
            int n = t + 1024 * i;
            float wt = s0 * wg[(n - 1) & (NMEM - 1)] + s1 * wg[n] + s2 * wg[(n + 1) & (NMEM - 1)];
            float wp = (wt > 0.f) ? __powf(wt, gamma) : 0.f;
            sc[n] = wp; lp += wp;
        }
        lp = wredsum(lp);
        if (lane == 0) red[w] = lp;
        __syncthreads();
        if (w == 0) { float v = red[lane]; v = wredsum(v); if (lane == 0) bcast = v + 1e-16f; }
        __syncthreads();
        float iZp = 1.f / bcast;

        #pragma unroll
        for (int i = 0; i < 4; i++) {
            int n = t + 1024 * i;
            g_ww[b * NMEM + n] = sc[n] * iZp;
        }
        __syncthreads();
    }

    // phase B: read score from stats + read addressing
    {
        float beta = g_pr[b * 8 + 0], knr = g_pr[b * 8 + 6];
        float akr  = g_pr[b * 8 + 7], aa  = g_pw[b * 8 + 7];
        float g = g_pr[b * 8 + 1], s0 = g_pr[b * 8 + 2], s1 = g_pr[b * 8 + 3];
        float s2p = g_pr[b * 8 + 4], gamma = g_pr[b * 8 + 5];

        float lm = __int_as_float(0xff800000);
        #pragma unroll
        for (int i = 0; i < 4; i++) {
            int n = t + 1024 * i;
            int row = b * NMEM + n;
            float wwv = g_ww[row];
            float d1 = g_st[0][row], d2 = g_st[1][row], ssv = g_st[2][row];
            float s2v = g_st[3][row], s3v = g_st[4][row], s4v = g_st[5][row], s5v = g_st[6][row];
            float dot = d1 - wwv * (d2 - akr);
            float n2 = ssv + wwv * (2.f * (s4v - s2v)) + wwv * wwv * (s3v - 2.f * s5v + aa);
            float v = beta * dot / (sqrtf(fmaxf(n2, 0.f)) * knr + 1e-16f);
            sc[n] = v; lm = fmaxf(lm, v);
        }
        lm = wredmax(lm);
        if (lane == 0) red[w] = lm;
        __syncthreads();
        if (w == 0) { float v = red[lane]; v = wredmax(v); if (lane == 0) bcast = v; }
        __syncthreads();
        float bm = bcast;

        float ls = 0.f;
        #pragma unroll
        for (int i = 0; i < 4; i++) {
            int n = t + 1024 * i;
            float pv = __expf(sc[n] - bm);
            sc[n] = pv; ls += pv;
        }
        ls = wredsum(ls);
        if (lane == 0) red[w] = ls;
        __syncthreads();
        if (w == 0) { float v = red[lane]; v = wredsum(v); if (lane == 0) bcast = v; }
        __syncthreads();
        float gZ = g / bcast, og = 1.f - g;

        #pragma unroll
        for (int i = 0; i < 4; i++) {
            int n = t + 1024 * i;
            wg[n] = fmaf(gZ, sc[n], og * wr0[b * NMEM + n]);
        }
        __syncthreads();

        float lp = 0.f;
        #pragma unroll
        for (int i = 0; i < 4; i++) {
            int n = t + 1024 * i;
            float wt = s0 * wg[(n - 1) & (NMEM - 1)] + s1 * wg[n] + s2p * wg[(n + 1) & (NMEM - 1)];
            float wp = (wt > 0.f) ? __powf(wt, gamma) : 0.f;
            sc[n] = wp; lp += wp;
        }
        lp = wredsum(lp);
        if (lane == 0) red[w] = lp;
        __syncthreads();
        if (w == 0) { float v = red[lane]; v = wredsum(v); if (lane == 0) bcast = v + 1e-16f; }
        __syncthreads();
        float iZp = 1.f / bcast;

        #pragma unroll
        for (int i = 0; i < 4; i++) {
            int n = t + 1024 * i;
            g_wr[b * NMEM + n] = sc[n] * iZp;
        }
    }
}

// ============ Kernel 5: r partials = w_r . mem2 ============
__global__ void __launch_bounds__(256) k_readvec(const float* __restrict__ mem)
{
    __shared__ float es4[M], as4[M];
    __shared__ float part[16][M + 4];
    int b = blockIdx.x, chunk = blockIdx.y;
    int t = threadIdx.x;
    int m4 = t & 15;
    int rgrp = t >> 4;
    if (t < M) { es4[t] = g_e[b * M + t]; as4[t] = g_a[b * M + t]; }
    __syncthreads();

    int m = m4 * 4;
    float4 ev = make_float4(es4[m], es4[m + 1], es4[m + 2], es4[m + 3]);
    float4 av = make_float4(as4[m], as4[m + 1], as4[m + 2], as4[m + 3]);

    float4 acc = make_float4(0.f, 0.f, 0.f, 0.f);
    int n0 = chunk * 128;
    #pragma unroll
    for (int k = 0; k < 8; k++) {
        int n = n0 + rgrp + 16 * k;
        int row = b * NMEM + n;
        float wwv = g_ww[row], wrv = g_wr[row];
        float4 v = *(const float4*)(mem + (size_t)row * M + m);
        float4 v2;
        v2.x = fmaf(v.x, 1.f - wwv * ev.x, wwv * av.x);
        v2.y = fmaf(v.y, 1.f - wwv * ev.y, wwv * av.y);
        v2.z = fmaf(v.z, 1.f - wwv * ev.z, wwv * av.z);
        v2.w = fmaf(v.w, 1.f - wwv * ev.w, wwv * av.w);
        acc.x = fmaf(wrv, v2.x, acc.x);
        acc.y = fmaf(wrv, v2.y, acc.y);
        acc.z = fmaf(wrv, v2.z, acc.z);
        acc.w = fmaf(wrv, v2.w, acc.w);
    }
    *(float4*)&part[rgrp][m] = acc;
    __syncthreads();

    if (t < M) {
        float s = 0.f;
        #pragma unroll
        for (int r = 0; r < 16; r++) s += part[r][t];
        g_rpart[(b * 32 + chunk) * M + t] = s;
    }
}

// ============ Kernel 6: decoder ============
__global__ void k_decode(const float* __restrict__ decW, const float* __restrict__ decb,
                         float* __restrict__ out)
{
    __shared__ float xs[H];
    __shared__ float rs[M];
    int b = blockIdx.x, t = threadIdx.x;
    xs[t] = g_xm[b * H + t];
    if (t < M) {
        float s = 0.f;
        #pragma unroll
        for (int c = 0; c < 32; c++) s += g_rpart[(b * 32 + c) * M + t];
        rs[t] = s;
    }
    __syncthreads();
    if (t < OUT) {
        float acc = decb[t];
        for (int hh = 0; hh < H; hh++) acc = fmaf(xs[hh], decW[hh * OUT + t], acc);
        for (int m = 0; m < M; m++) acc = fmaf(rs[m], decW[(H + m) * OUT + t], acc);
        out[b * OUT + t] = acc;
    }
}

// ---------------- launch ----------------
extern "C" void kernel_launch(void* const* d_in, const int* in_sizes, int n_in,
                              void* d_out, int out_size)
{
    const float* x      = (const float*)d_in[0];
    const float* r0     = (const float*)d_in[1];
    const float* sr0    = (const float*)d_in[2];
    const float* si0    = (const float*)d_in[3];
    const float* w_r0   = (const float*)d_in[4];
    const float* w_w0   = (const float*)d_in[5];
    const float* mem    = (const float*)d_in[6];
    const float* encW   = (const float*)d_in[7];
    const float* encb   = (const float*)d_in[8];
    const float* log_dt = (const float*)d_in[9];
    const float* logAr  = (const float*)d_in[10];
    const float* Aim    = (const float*)d_in[11];
    const float* Cre    = (const float*)d_in[12];
    const float* Cim    = (const float*)d_in[13];
    const float* Dv     = (const float*)d_in[14];
    const float* decW   = (const float*)d_in[15];
    const float* decb   = (const float*)d_in[16];
    const float* readW  = (const float*)d_in[17];
    const float* readb  = (const float*)d_in[18];
    const float* writeW = (const float*)d_in[19];
    const float* writeb = (const float*)d_in[20];
    float* out = (float*)d_out;

    k_encode_scan<<<dim3(B, H / 16), 256>>>(x, r0, sr0, si0, encW, encb,
                                            log_dt, logAr, Aim, Cre, Cim, Dv);
    k_heads<<<B, 288>>>(writeW, writeb, readW, readb);
    k_pass1<<<512, 256>>>(mem);
    k_addr2<<<B, 1024>>>(w_w0, w_r0);
    k_readvec<<<dim3(B, 32), 256>>>(mem);
    k_decode<<<B, 256>>>(decW, decb, out);
}

// round 12
// speedup vs baseline: 1.3954x; 1.2367x over previous
#include <cuda_runtime.h>
#include <math.h>

#define B 32
#define L 256
#define EXT 64
#define H 256
#define M 64
#define NMEM 4096
#define NST 32
#define OUT 64

typedef unsigned long long ull;

// ---------------- scratch (device globals; no allocation) ----------------
__device__ float g_xm[B * H];
__device__ float g_kw[B * M], g_e[B * M], g_a[B * M], g_kr[B * M];
__device__ float g_pw[B * 8], g_pr[B * 8];
__device__ float g_score[B * NMEM];
__device__ float g_st[7][B * NMEM];    // d1,d2,ss,s2,s3,s4,s5
__device__ float g_ww[B * NMEM], g_wr[B * NMEM];
__device__ float g_rpart[B * 32 * M];

// ---------------- helpers ----------------
__device__ __forceinline__ float wredsum(float v) {
    #pragma unroll
    for (int o = 16; o > 0; o >>= 1) v += __shfl_xor_sync(0xffffffffu, v, o);
    return v;
}
__device__ __forceinline__ float gredsum16(float v) {
    #pragma unroll
    for (int o = 8; o > 0; o >>= 1) v += __shfl_xor_sync(0xffffffffu, v, o);
    return v;
}
__device__ __forceinline__ float wredmax(float v) {
    #pragma unroll
    for (int o = 16; o > 0; o >>= 1) v = fmaxf(v, __shfl_xor_sync(0xffffffffu, v, o));
    return v;
}
__device__ __forceinline__ float softplus_f(float x) {
    return (x > 20.f) ? x : log1pf(expf(x));
}
__device__ __forceinline__ float sigmoid_f(float x) {
    return 1.f / (1.f + expf(-x));
}
__device__ __forceinline__ ull pack2(float lo, float hi) {
    ull r; asm("mov.b64 %0,{%1,%2};" : "=l"(r) : "f"(lo), "f"(hi)); return r;
}
__device__ __forceinline__ void unpack2(ull v, float& lo, float& hi) {
    asm("mov.b64 {%0,%1},%2;" : "=f"(lo), "=f"(hi) : "l"(v));
}
__device__ __forceinline__ ull f2fma(ull a, ull b, ull c) {
    ull d; asm("fma.rn.f32x2 %0,%1,%2,%3;" : "=l"(d) : "l"(a), "l"(b), "l"(c)); return d;
}
__device__ __forceinline__ ull f2mul(ull a, ull b) {
    ull d; asm("mul.rn.f32x2 %0,%1,%2;" : "=l"(d) : "l"(a), "l"(b)); return d;
}

// ============ Kernel 1: register-tiled encoder GEMM + ILP-4 S4D scan ============
// grid (B, H/16), block 256.
// GEMM: thread = 4l x 4h tile; e-tiled (16 e per tile, 4 tiles).
// Scan: warp = 2 heads; 16-lane half packs 2 states/lane; 4-chunk ILP.
__global__ void __launch_bounds__(256) k_encode_scan(
    const float* __restrict__ x, const float* __restrict__ r0,
    const float* __restrict__ sr0, const float* __restrict__ si0,
    const float* __restrict__ encW, const float* __restrict__ encb,
    const float* __restrict__ log_dt, const float* __restrict__ logAr,
    const float* __restrict__ Aim, const float* __restrict__ Cre,
    const float* __restrict__ Cim, const float* __restrict__ Dv)
{
    __shared__ float Ws[64 * 16];        // [e][hh], 4KB
    __shared__ float cbs[16];
    __shared__ __align__(16) float xsT[16 * 264];   // [e_local][l], 16.9KB
    __shared__ __align__(16) float us[16 * 264];    // [hh][l], 16.9KB

    int b = blockIdx.x, hg = blockIdx.y;
    int t = threadIdx.x;

    // load encoder weights for this block's 16 heads
    for (int i = t; i < 64 * 16; i += 256) {
        int e = i >> 4, hh = i & 15;
        Ws[i] = encW[e * H + hg * 16 + hh];
    }

    // effective bias: enc_b[h] + r0 . enc_W[EXT:,h]; thread t = (hh, p)
    {
        int hh_b = t >> 4, p_b = t & 15;
        float cb = 0.f;
        #pragma unroll
        for (int m = p_b; m < M; m += 16)
            cb = fmaf(r0[b * M + m], encW[(EXT + m) * H + hg * 16 + hh_b], cb);
        cb = gredsum16(cb) + encb[hg * 16 + hh_b];
        if (p_b == 0) cbs[hh_b] = cb;
    }
    __syncthreads();

    // ---- GEMM: acc[i][j] = sum_e x[l0+i][e] * W[e][h0+j] ----
    int lq = t >> 2, hq = t & 3;       // l-quad 0..63, h-quad 0..3
    float acc[4][4];
    #pragma unroll
    for (int i = 0; i < 4; i++)
        #pragma unroll
        for (int j = 0; j < 4; j++) acc[i][j] = 0.f;

    for (int et = 0; et < 4; et++) {
        __syncthreads();
        // load x e-tile transposed: xsT[e_local][l]
        #pragma unroll
        for (int k = 0; k < 4; k++) {
            int linear = k * 256 + t;
            int l = linear >> 2, esub = linear & 3;
            float4 xv = *(const float4*)&x[((size_t)(b * L + l)) * EXT + et * 16 + esub * 4];
            xsT[(esub * 4 + 0) * 264 + l] = xv.x;
            xsT[(esub * 4 + 1) * 264 + l] = xv.y;
            xsT[(esub * 4 + 2) * 264 + l] = xv.z;
            xsT[(esub * 4 + 3) * 264 + l] = xv.w;
        }
        __syncthreads();

        #pragma unroll
        for (int e = 0; e < 16; e++) {
            float4 xv = *(const float4*)&xsT[e * 264 + lq * 4];
            float4 wv = *(const float4*)&Ws[(et * 16 + e) * 16 + hq * 4];
            acc[0][0] = fmaf(xv.x, wv.x, acc[0][0]);
            acc[0][1] = fmaf(xv.x, wv.y, acc[0][1]);
            acc[0][2] = fmaf(xv.x, wv.z, acc[0][2]);
            acc[0][3] = fmaf(xv.x, wv.w, acc[0][3]);
            acc[1][0] = fmaf(xv.y, wv.x, acc[1][0]);
            acc[1][1] = fmaf(xv.y, wv.y, acc[1][1]);
            acc[1][2] = fmaf(xv.y, wv.z, acc[1][2]);
            acc[1][3] = fmaf(xv.y, wv.w, acc[1][3]);
            acc[2][0] = fmaf(xv.z, wv.x, acc[2][0]);
            acc[2][1] = fmaf(xv.z, wv.y, acc[2][1]);
            acc[2][2] = fmaf(xv.z, wv.z, acc[2][2]);
            acc[2][3] = fmaf(xv.z, wv.w, acc[2][3]);
            acc[3][0] = fmaf(xv.w, wv.x, acc[3][0]);
            acc[3][1] = fmaf(xv.w, wv.y, acc[3][1]);
            acc[3][2] = fmaf(xv.w, wv.z, acc[3][2]);
            acc[3][3] = fmaf(xv.w, wv.w, acc[3][3]);
        }
    }
    __syncthreads();

    // write u (+bias): us[h][l]
    #pragma unroll
    for (int j = 0; j < 4; j++) {
        int hh = hq * 4 + j;
        float cb = cbs[hh];
        float4 uv = make_float4(acc[0][j] + cb, acc[1][j] + cb,
                                acc[2][j] + cb, acc[3][j] + cb);
        *(float4*)&us[hh * 264 + lq * 4] = uv;
    }
    __syncthreads();

    // ---- scan phase ----
    int w = t >> 5, lane = t & 31;
    int sel = lane >> 4, p = lane & 15;
    int slot = w * 2 + sel;            // head within block
    int h = hg * 16 + slot;

    float usum = 0.f;
    #pragma unroll
    for (int k = 0; k < 16; k++) usum += us[slot * 264 + p + 16 * k];
    usum = gredsum16(usum);

    int n0 = 2 * p;
    float dt = expf(log_dt[h]);
    float ar_s[2], ai_s[2], dAr_s[2], dAi_s[2];
    #pragma unroll
    for (int s = 0; s < 2; s++) {
        int idx = h * NST + n0 + s;
        ar_s[s] = -expf(logAr[idx]);
        ai_s[s] = Aim[idx];
        float er = expf(dt * ar_s[s]);
        dAr_s[s] = er * cosf(dt * ai_s[s]);
        dAi_s[s] = er * sinf(dt * ai_s[s]);
    }
    ull dAr2  = pack2(dAr_s[0], dAr_s[1]);
    ull dAi2  = pack2(dAi_s[0], dAi_s[1]);
    ull ndAi2 = pack2(-dAi_s[0], -dAi_s[1]);

    ull tr[4] = {0, 0, 0, 0}, ti[4] = {0, 0, 0, 0};
    #pragma unroll 4
    for (int j = 0; j < 64; j++) {
        #pragma unroll
        for (int c = 0; c < 4; c++) {
            float uv = us[slot * 264 + c * 64 + j];
            ull u2 = pack2(uv, uv);
            ull tA = f2fma(ndAi2, ti[c], u2);
            ull trn = f2fma(dAr2, tr[c], tA);
            ull tB = f2mul(dAr2, ti[c]);
            ti[c] = f2fma(dAi2, tr[c], tB);
            tr[c] = trn;
        }
    }

    // combine chunks in-lane: T = T3 + P*T2 + P^2*T1 + P^3*T0, P = dA^64
    float Trs[2], Tis[2];
    #pragma unroll
    for (int s = 0; s < 2; s++) {
        float e64 = expf(64.f * dt * ar_s[s]);
        float ang = 64.f * dt * ai_s[s];
        float Prr = e64 * cosf(ang), Pii = e64 * sinf(ang);
        float W2r = Prr, W2i = Pii;
        float W1r = Prr * Prr - Pii * Pii, W1i = 2.f * Prr * Pii;
        float W0r = W1r * Prr - W1i * Pii, W0i = W1i * Prr + W1r * Pii;
        float t3r, t3i, t2r, t2i, t1r, t1i, t0r, t0i, dum;
        if (s == 0) {
            unpack2(tr[3], t3r, dum); unpack2(ti[3], t3i, dum);
            unpack2(tr[2], t2r, dum); unpack2(ti[2], t2i, dum);
            unpack2(tr[1], t1r, dum); unpack2(ti[1], t1i, dum);
            unpack2(tr[0], t0r, dum); unpack2(ti[0], t0i, dum);
        } else {
            unpack2(tr[3], dum, t3r); unpack2(ti[3], dum, t3i);
            unpack2(tr[2], dum, t2r); unpack2(ti[2], dum, t2i);
            unpack2(tr[1], dum, t1r); unpack2(ti[1], dum, t1i);
            unpack2(tr[0], dum, t0r); unpack2(ti[0], dum, t0i);
        }
        Trs[s] = t3r + (W2r * t2r - W2i * t2i) + (W1r * t1r - W1i * t1i) + (W0r * t0r - W0i * t0i);
        Tis[s] = t3i + (W2i * t2r + W2r * t2i) + (W1i * t1r + W1r * t1i) + (W0i * t0r + W0r * t0i);
    }

    // closed form: sum_l s_l = Geo*s0 + (-1/A)*(sum_u - dA*T)
    float val = 0.f;
    #pragma unroll
    for (int s = 0; s < 2; s++) {
        int idx = h * NST + n0 + s;
        float ar = ar_s[s], ai = ai_s[s];
        float dar = dAr_s[s], dai = dAi_s[s];
        float xr = dar * Trs[s] - dai * Tis[s];
        float xi = dai * Trs[s] + dar * Tis[s];
        float wr = usum - xr, wi = -xi;
        float den = ar * ar + ai * ai;
        float invr = -ar / den, invi = ai / den;
        float Sr = invr * wr - invi * wi;
        float Si = invr * wi + invi * wr;
        float s0r = sr0[b * H * NST + idx], s0i = si0[b * H * NST + idx];
        if (s0r != 0.f || s0i != 0.f) {
            float eL = expf((float)L * dt * ar);
            float phi = (float)L * dt * ai;
            float dALr = eL * cosf(phi), dALi = eL * sinf(phi);
            float numr = 1.f - dALr, numi = -dALi;
            float omr = 1.f - dar, omi = -dai;
            float r2 = omr * omr + omi * omi;
            float qr = (numr * omr + numi * omi) / r2;
            float qi = (numi * omr - numr * omi) / r2;
            float gr = dar * qr - dai * qi;
            float gi = dai * qr + dar * qi;
            Sr += gr * s0r - gi * s0i;
            Si += gr * s0i + gi * s0r;
        }
        val += Cre[idx] * Sr - Cim[idx] * Si;
    }
    val = gredsum16(val);
    if (p == 0)
        g_xm[b * H + h] = (2.f * val + (Dv[h] + 1.f) * usum) * (1.f / (float)L);
}

// ============ Kernel 2: head projections + per-batch consts ============
__global__ void k_heads(
    const float* __restrict__ writeW, const float* __restrict__ writeb,
    const float* __restrict__ readW,  const float* __restrict__ readb)
{
    __shared__ float xs[H];
    __shared__ float sow[3 * M + 6];
    __shared__ float sorh[M + 6];
    int b = blockIdx.x, t = threadIdx.x;
    if (t < H) xs[t] = g_xm[b * H + t];
    __syncthreads();

    if (t < 198) {
        float acc = writeb[t];
        for (int hh = 0; hh < H; hh++) acc = fmaf(xs[hh], writeW[hh * 198 + t], acc);
        sow[t] = acc;
    } else if (t < 268) {
        int j = t - 198;
        float acc = readb[j];
        for (int hh = 0; hh < H; hh++) acc = fmaf(xs[hh], readW[hh * 70 + j], acc);
        sorh[j] = acc;
    }
    __syncthreads();

    if (t < M) {
        g_kw[b * M + t] = sow[t];
        g_e[b * M + t]  = sigmoid_f(sow[M + 6 + t]);
        g_a[b * M + t]  = sow[2 * M + 6 + t];
        g_kr[b * M + t] = sorh[t];
    } else if (t == M) {
        float beta = softplus_f(sow[M]);
        float g    = sigmoid_f(sow[M + 1]);
        float m3 = fmaxf(sow[M + 2], fmaxf(sow[M + 3], sow[M + 4]));
        float e0 = expf(sow[M + 2] - m3), e1 = expf(sow[M + 3] - m3), e2 = expf(sow[M + 4] - m3);
        float Z = e0 + e1 + e2;
        float gamma = 1.f + softplus_f(sow[M + 5]);
        float nk = 0.f;
        for (int m = 0; m < M; m++) { float v = sow[m]; nk += v * v; }
        g_pw[b * 8 + 0] = beta; g_pw[b * 8 + 1] = g;
        g_pw[b * 8 + 2] = e0 / Z; g_pw[b * 8 + 3] = e1 / Z; g_pw[b * 8 + 4] = e2 / Z;
        g_pw[b * 8 + 5] = gamma; g_pw[b * 8 + 6] = sqrtf(nk);
    } else if (t == M + 1) {
        float beta = softplus_f(sorh[M]);
        float g    = sigmoid_f(sorh[M + 1]);
        float m3 = fmaxf(sorh[M + 2], fmaxf(sorh[M + 3], sorh[M + 4]));
        float e0 = expf(sorh[M + 2] - m3), e1 = expf(sorh[M + 3] - m3), e2 = expf(sorh[M + 4] - m3);
        float Z = e0 + e1 + e2;
        float gamma = 1.f + softplus_f(sorh[M + 5]);
        float nk = 0.f;
        for (int m = 0; m < M; m++) { float v = sorh[m]; nk += v * v; }
        g_pr[b * 8 + 0] = beta; g_pr[b * 8 + 1] = g;
        g_pr[b * 8 + 2] = e0 / Z; g_pr[b * 8 + 3] = e1 / Z; g_pr[b * 8 + 4] = e2 / Z;
        g_pr[b * 8 + 5] = gamma; g_pr[b * 8 + 6] = sqrtf(nk);
    } else if (t == M + 2) {
        float akr = 0.f, aa = 0.f;
        for (int m = 0; m < M; m++) {
            float av = sow[2 * M + 6 + m];
            akr = fmaf(av, sorh[m], akr);
            aa  = fmaf(av, av, aa);
        }
        g_pr[b * 8 + 7] = akr;
        g_pw[b * 8 + 7] = aa;
    }
}

// ============ Kernel 3: mem pass via smem column tiles (no shuffles) ============
// grid 512 (16 blocks/batch), block 256; thread owns one row, 4 column tiles of 16.
__global__ void __launch_bounds__(256) k_pass1(const float* __restrict__ mem)
{
    __shared__ float tile[256 * 17];   // [row][col] stride 17 (conflict-free)
    __shared__ float kw[M], kr_[M], ekr[M], ev[M], e2v[M], av[M], eav[M];
    int t = threadIdx.x;
    int b = blockIdx.x >> 4;
    int rowbase = blockIdx.x * 256;

    if (t < M) {
        float kwv = g_kw[b * M + t];
        float krv = g_kr[b * M + t];
        float e_  = g_e[b * M + t];
        float a_  = g_a[b * M + t];
        kw[t] = kwv; kr_[t] = krv; ekr[t] = e_ * krv;
        ev[t] = e_; e2v[t] = e_ * e_; av[t] = a_; eav[t] = e_ * a_;
    }

    float dw = 0.f, ss = 0.f, d1 = 0.f, d2 = 0.f, s2 = 0.f, s3 = 0.f, s4 = 0.f, s5 = 0.f;

    for (int ct = 0; ct < 4; ct++) {
        __syncthreads();
        #pragma unroll
        for (int k = 0; k < 4; k++) {
            int linear = k * 256 + t;
            int l = linear >> 2, f4 = linear & 3;
            float4 v = *(const float4*)(mem + (size_t)(rowbase + l) * M + ct * 16 + f4 * 4);
            tile[l * 17 + f4 * 4 + 0] = v.x;
            tile[l * 17 + f4 * 4 + 1] = v.y;
            tile[l * 17 + f4 * 4 + 2] = v.z;
            tile[l * 17 + f4 * 4 + 3] = v.w;
        }
        __syncthreads();

        #pragma unroll
        for (int c = 0; c < 16; c++) {
            float v = tile[t * 17 + c];
            int mm = ct * 16 + c;
            float v2 = v * v;
            dw = fmaf(v, kw[mm],  dw);
            ss += v2;
            d1 = fmaf(v, kr_[mm], d1);
            d2 = fmaf(v, ekr[mm], d2);
            s2 = fmaf(v2, ev[mm],  s2);
            s3 = fmaf(v2, e2v[mm], s3);
            s4 = fmaf(v, av[mm],  s4);
            s5 = fmaf(v, eav[mm], s5);
        }
    }

    int row = rowbase + t;
    float beta = g_pw[b * 8 + 0], knw = g_pw[b * 8 + 6];
    g_score[row] = beta * dw / (sqrtf(ss) * knw + 1e-16f);
    g_st[0][row] = d1; g_st[1][row] = d2; g_st[2][row] = ss;
    g_st[3][row] = s2; g_st[4][row] = s3; g_st[5][row] = s4; g_st[6][row] = s5;
}

// ============ Kernel 4: write addressing + read score + read addressing ============
__global__ void __launch_bounds__(1024) k_addr2(
    const float* __restrict__ ww0, const float* __restrict__ wr0)
{
    __shared__ float sc[NMEM];
    __shared__ float wg[NMEM];
    __shared__ float red[32];
    __shared__ float bcast;
    int b = blockIdx.x, t = threadIdx.x;
    int lane = t & 31, w = t >> 5;

    // phase A: write addressing
    {
        float g = g_pw[b * 8 + 1], s0 = g_pw[b * 8 + 2], s1 = g_pw[b * 8 + 3];
        float s2 = g_pw[b * 8 + 4], gamma = g_pw[b * 8 + 5];

        float lm = __int_as_float(0xff800000);
        #pragma unroll
        for (int i = 0; i < 4; i++) {
            int n = t + 1024 * i;
            float v = g_score[b * NMEM + n];
            sc[n] = v; lm = fmaxf(lm, v);
        }
        lm = wredmax(lm);
        if (lane == 0) red[w] = lm;
        __syncthreads();
        if (w == 0) { float v = red[lane]; v = wredmax(v); if (lane == 0) bcast = v; }
        __syncthreads();
        float bm = bcast;

        float ls = 0.f;
        #pragma unroll
        for (int i = 0; i < 4; i++) {
            int n = t + 1024 * i;
            float pv = __expf(sc[n] - bm);
            sc[n] = pv; ls += pv;
        }
        ls = wredsum(ls);
        if (lane == 0) red[w] = ls;
        __syncthreads();
        if (w == 0) { float v = red[lane]; v = wredsum(v); if (lane == 0) bcast = v; }
        __syncthreads();
        float gZ = g / bcast, og = 1.f - g;

        #pragma unroll
        for (int i = 0; i < 4; i++) {
            int n = t + 1024 * i;
            wg[n] = fmaf(gZ, sc[n], og * ww0[b * NMEM + n]);
        }
        __syncthreads();

        float lp = 0.f;
        #pragma unroll
        for (int i = 0; i < 4; i++) {
            int n = t + 1024 * i;
            float wt = s0 * wg[(n - 1) & (NMEM - 1)] + s1 * wg[n] + s2 * wg[(n + 1) & (NMEM - 1)];
            float wp = (wt > 0.f) ? __powf(wt, gamma) : 0.f;
            sc[n] = wp; lp += wp;
        }
        lp = wredsum(lp);
        if (lane == 0) red[w] = lp;
        __syncthreads();
        if (w == 0) { float v = red[lane]; v = wredsum(v); if (lane == 0) bcast = v + 1e-16f; }
        __syncthreads();
        float iZp = 1.f / bcast;

        #pragma unroll
        for (int i = 0; i < 4; i++) {
            int n = t + 1024 * i;
            g_ww[b * NMEM + n] = sc[n] * iZp;
        }
        __syncthreads();
    }

    // phase B: read score from stats + read addressing
    {
        float beta = g_pr[b * 8 + 0], knr = g_pr[b * 8 + 6];
        float akr  = g_pr[b * 8 + 7], aa  = g_pw[b * 8 + 7];
        float g = g_pr[b * 8 + 1], s0 = g_pr[b * 8 + 2], s1 = g_pr[b * 8 + 3];
        float s2p = g_pr[b * 8 + 4], gamma = g_pr[b * 8 + 5];

        float lm = __int_as_float(0xff800000);
        #pragma unroll
        for (int i = 0; i < 4; i++) {
            int n = t + 1024 * i;
            int row = b * NMEM + n;
            float wwv = g_ww[row];
            float d1 = g_st[0][row], d2 = g_st[1][row], ssv = g_st[2][row];
            float s2v = g_st[3][row], s3v = g_st[4][row], s4v = g_st[5][row], s5v = g_st[6][row];
            float dot = d1 - wwv * (d2 - akr);
            float n2 = ssv + wwv * (2.f * (s4v - s2v)) + wwv * wwv * (s3v - 2.f * s5v + aa);
            float v = beta * dot / (sqrtf(fmaxf(n2, 0.f)) * knr + 1e-16f);
            sc[n] = v; lm = fmaxf(lm, v);
        }
        lm = wredmax(lm);
        if (lane == 0) red[w] = lm;
        __syncthreads();
        if (w == 0) { float v = red[lane]; v = wredmax(v); if (lane == 0) bcast = v; }
        __syncthreads();
        float bm = bcast;

        float ls = 0.f;
        #pragma unroll
        for (int i = 0; i < 4; i++) {
            int n = t + 1024 * i;
            float pv = __expf(sc[n] - bm);
            sc[n] = pv; ls += pv;
        }
        ls = wredsum(ls);
        if (lane == 0) red[w] = ls;
        __syncthreads();
        if (w == 0) { float v = red[lane]; v = wredsum(v); if (lane == 0) bcast = v; }
        __syncthreads();
        float gZ = g / bcast, og = 1.f - g;

        #pragma unroll
        for (int i = 0; i < 4; i++) {
            int n = t + 1024 * i;
            wg[n] = fmaf(gZ, sc[n], og * wr0[b * NMEM + n]);
        }
        __syncthreads();

        float lp = 0.f;
        #pragma unroll
        for (int i = 0; i < 4; i++) {
            int n = t + 1024 * i;
            float wt = s0 * wg[(n - 1) & (NMEM - 1)] + s1 * wg[n] + s2p * wg[(n + 1) & (NMEM - 1)];
            float wp = (wt > 0.f) ? __powf(wt, gamma) : 0.f;
            sc[n] = wp; lp += wp;
        }
        lp = wredsum(lp);
        if (lane == 0) red[w] = lp;
        __syncthreads();
        if (w == 0) { float v = red[lane]; v = wredsum(v); if (lane == 0) bcast = v + 1e-16f; }
        __syncthreads();
        float iZp = 1.f / bcast;

        #pragma unroll
        for (int i = 0; i < 4; i++) {
            int n = t + 1024 * i;
            g_wr[b * NMEM + n] = sc[n] * iZp;
        }
    }
}

// ============ Kernel 5: r partials = w_r . mem2 ============
__global__ void __launch_bounds__(256) k_readvec(const float* __restrict__ mem)
{
    __shared__ float es4[M], as4[M];
    __shared__ float part[16][M + 4];
    int b = blockIdx.x, chunk = blockIdx.y;
    int t = threadIdx.x;
    int m4 = t & 15;
    int rgrp = t >> 4;
    if (t < M) { es4[t] = g_e[b * M + t]; as4[t] = g_a[b * M + t]; }
    __syncthreads();

    int m = m4 * 4;
    float4 ev = make_float4(es4[m], es4[m + 1], es4[m + 2], es4[m + 3]);
    float4 av = make_float4(as4[m], as4[m + 1], as4[m + 2], as4[m + 3]);

    float4 acc = make_float4(0.f, 0.f, 0.f, 0.f);
    int n0 = chunk * 128;
    #pragma unroll
    for (int k = 0; k < 8; k++) {
        int n = n0 + rgrp + 16 * k;
        int row = b * NMEM + n;
        float wwv = g_ww[row], wrv = g_wr[row];
        float4 v = *(const float4*)(mem + (size_t)row * M + m);
        float4 v2;
        v2.x = fmaf(v.x, 1.f - wwv * ev.x, wwv * av.x);
        v2.y = fmaf(v.y, 1.f - wwv * ev.y, wwv * av.y);
        v2.z = fmaf(v.z, 1.f - wwv * ev.z, wwv * av.z);
        v2.w = fmaf(v.w, 1.f - wwv * ev.w, wwv * av.w);
        acc.x = fmaf(wrv, v2.x, acc.x);
        acc.y = fmaf(wrv, v2.y, acc.y);
        acc.z = fmaf(wrv, v2.z, acc.z);
        acc.w = fmaf(wrv, v2.w, acc.w);
    }
    *(float4*)&part[rgrp][m] = acc;
    __syncthreads();

    if (t < M) {
        float s = 0.f;
        #pragma unroll
        for (int r = 0; r < 16; r++) s += part[r][t];
        g_rpart[(b * 32 + chunk) * M + t] = s;
    }
}

// ============ Kernel 6: decoder ============
__global__ void k_decode(const float* __restrict__ decW, const float* __restrict__ decb,
                         float* __restrict__ out)
{
    __shared__ float xs[H];
    __shared__ float rs[M];
    int b = blockIdx.x, t = threadIdx.x;
    xs[t] = g_xm[b * H + t];
    if (t < M) {
        float s = 0.f;
        #pragma unroll
        for (int c = 0; c < 32; c++) s += g_rpart[(b * 32 + c) * M + t];
        rs[t] = s;
    }
    __syncthreads();
    if (t < OUT) {
        float acc = decb[t];
        for (int hh = 0; hh < H; hh++) acc = fmaf(xs[hh], decW[hh * OUT + t], acc);
        for (int m = 0; m < M; m++) acc = fmaf(rs[m], decW[(H + m) * OUT + t], acc);
        out[b * OUT + t] = acc;
    }
}

// ---------------- launch ----------------
extern "C" void kernel_launch(void* const* d_in, const int* in_sizes, int n_in,
                              void* d_out, int out_size)
{
    const float* x      = (const float*)d_in[0];
    const float* r0     = (const float*)d_in[1];
    const float* sr0    = (const float*)d_in[2];
    const float* si0    = (const float*)d_in[3];
    const float* w_r0   = (const float*)d_in[4];
    const float* w_w0   = (const float*)d_in[5];
    const float* mem    = (const float*)d_in[6];
    const float* encW   = (const float*)d_in[7];
    const float* encb   = (const float*)d_in[8];
    const float* log_dt = (const float*)d_in[9];
    const float* logAr  = (const float*)d_in[10];
    const float* Aim    = (const float*)d_in[11];
    const float* Cre    = (const float*)d_in[12];
    const float* Cim    = (const float*)d_in[13];
    const float* Dv     = (const float*)d_in[14];
    const float* decW   = (const float*)d_in[15];
    const float* decb   = (const float*)d_in[16];
    const float* readW  = (const float*)d_in[17];
    const float* readb  = (const float*)d_in[18];
    const float* writeW = (const float*)d_in[19];
    const float* writeb = (const float*)d_in[20];
    float* out = (float*)d_out;

    k_encode_scan<<<dim3(B, H / 16), 256>>>(x, r0, sr0, si0, encW, encb,
                                            log_dt, logAr, Aim, Cre, Cim, Dv);
    k_heads<<<B, 288>>>(writeW, writeb, readW, readb);
    k_pass1<<<512, 256>>>(mem);
    k_addr2<<<B, 1024>>>(w_w0, w_r0);
    k_readvec<<<dim3(B, 32), 256>>>(mem);
    k_decode<<<B, 256>>>(decW, decb, out);
}